// round 11
// baseline (speedup 1.0000x reference)
#include <cuda_runtime.h>
#include <cuda_bf16.h>
#include <cstdint>

#define NN 20000
#define SS 4096
#define EE 640000
#define DD 256
#define M_PAD 20096   // 157 * 128

// ---------------- scratch (zero-initialized device globals) ----------------
__device__ float g_h[M_PAD * DD];          // current node features (tf32-rounded)
__device__ float g_tmp[M_PAD * DD];        // h @ W
__device__ float g_wt[DD * DD];            // W^T (K-major), tf32-rounded
__device__ int   g_cnt[NN];
__device__ int   g_off[NN + 1];
__device__ int   g_cur[NN];
__device__ int2  g_edge[EE];               // packed (src_row, attr_bits), CSR order
// embed closed-form tables
__device__ __align__(16) unsigned char g_mtab[SS];  // j -> interval index (0..16)
__device__ int g_ck[16];                            // rank per k
__device__ int g_dirk[16];                          // 0 = suffix active, 1 = prefix active

// ---------------- helpers ----------------
__device__ __forceinline__ uint32_t smem_u32(const void* p) {
    uint32_t a;
    asm("{ .reg .u64 t; cvta.to.shared.u64 t, %1; cvt.u32.u64 %0, t; }" : "=r"(a) : "l"(p));
    return a;
}
__device__ __forceinline__ float to_tf32(float x) {
    uint32_t u;
    asm("cvt.rna.tf32.f32 %0, %1;" : "=r"(u) : "f"(x));
    return __uint_as_float(u);
}
#define CP_ASYNC16(s, g) asm volatile("cp.async.cg.shared.global [%0], [%1], 16;" :: "r"(s), "l"(g) : "memory")
#define CP_COMMIT()      asm volatile("cp.async.commit_group;" ::: "memory")
#define CP_WAIT(n)       asm volatile("cp.async.wait_group %0;" :: "n"(n) : "memory")

__device__ __forceinline__ void mma_tf32(float* d, const uint32_t* a, const uint32_t* b) {
    asm volatile(
        "mma.sync.aligned.m16n8k8.row.col.f32.tf32.tf32.f32 "
        "{%0,%1,%2,%3}, {%4,%5,%6,%7}, {%8,%9}, {%0,%1,%2,%3};"
        : "+f"(d[0]), "+f"(d[1]), "+f"(d[2]), "+f"(d[3])
        : "r"(a[0]), "r"(a[1]), "r"(a[2]), "r"(a[3]), "r"(b[0]), "r"(b[1]));
}

// =====================================================================
// prep (block 0) + zero_counts (blocks 1..79)
// =====================================================================
__global__ void prep_zero_kernel(const float* __restrict__ w1, const float* __restrict__ b1) {
    const int tid = threadIdx.x;
    if (blockIdx.x != 0) {
        int i = (blockIdx.x - 1) * 256 + tid;
        if (i < NN) g_cnt[i] = 0;
        return;
    }
    __shared__ int s_B[16];
    __shared__ int s_bnd[16];
    if (tid < 16) {
        float w = w1[tid], b = b1[tid];
        int B, dir;
        if (w > 0.0f) {
            float t = -b / w;
            int cand = (int)floorf(t) - 1;
            if (cand < 0) cand = 0;
            if (cand > SS) cand = SS;
            while (cand < SS && !(fmaf((float)cand, w, b) > 0.0f)) cand++;
            B = cand; dir = 0;
        } else if (w < 0.0f) {
            float t = -b / w;
            int cand = (int)floorf(t) - 1;
            if (cand < 0) cand = 0;
            if (cand > SS) cand = SS;
            while (cand < SS && (fmaf((float)cand, w, b) > 0.0f)) cand++;
            B = cand; dir = 1;
        } else {
            if (b > 0.0f) { B = 0; dir = 0; }
            else          { B = 0; dir = 1; }
        }
        s_B[tid] = B;
        g_dirk[tid] = dir;
    }
    __syncthreads();
    if (tid < 16) {
        int Bk = s_B[tid], pos = 0;
#pragma unroll
        for (int i = 0; i < 16; i++) {
            int Bi = s_B[i];
            if (Bi < Bk || (Bi == Bk && i < tid)) pos++;
        }
        s_bnd[pos] = Bk;
    }
    __syncthreads();
    if (tid < 16) {
        int Bk = s_B[tid], c = 0;
#pragma unroll
        for (int i = 0; i < 16; i++) c += (s_bnd[i] <= Bk) ? 1 : 0;
        g_ck[tid] = c;
    }
    for (int j = tid; j < SS; j += blockDim.x) {
        int m = 0;
#pragma unroll
        for (int i = 0; i < 16; i++) m += (s_bnd[i] <= j) ? 1 : 0;
        g_mtab[j] = (unsigned char)m;
    }
}

// =====================================================================
// Row embedding v4: 2 rows/block, zero-skip, per-warp buckets,
// parallel bucket reduction
// =====================================================================
__global__ __launch_bounds__(256) void row_embed_kernel(
        const float* __restrict__ init,
        const float* __restrict__ w1, const float* __restrict__ b1,
        const float* __restrict__ w2, const float* __restrict__ b2) {
    __shared__ unsigned char s_mtab[SS];
    __shared__ uint32_t s_buck[8][17];
    __shared__ uint32_t s_tot[17];
    __shared__ float s_sufS[18];
    __shared__ int   s_sufC[18];
    __shared__ float s_fin[16];
    const int tid = threadIdx.x;
    const int wid = tid >> 5;
    const int row0 = blockIdx.x * 2;

    ((uint4*)s_mtab)[tid] = ((const uint4*)g_mtab)[tid];

    // load both rows up front (8 coalesced LDG.128, MLP 8)
    const float4* rp0 = (const float4*)(init + (size_t)row0 * SS);
    const float4* rp1 = rp0 + (SS / 4);
    float4 va[4], vb[4];
#pragma unroll
    for (int i = 0; i < 4; i++) va[i] = rp0[i * 256 + tid];
#pragma unroll
    for (int i = 0; i < 4; i++) vb[i] = rp1[i * 256 + tid];

    const float w2t[1] = {0.0f}; (void)w2t;

#pragma unroll 1
    for (int r = 0; r < 2; r++) {
        if (tid < 136) ((uint32_t*)s_buck)[tid] = 0u;
        __syncthreads();

        float4 vv[4];
#pragma unroll
        for (int i = 0; i < 4; i++) vv[i] = r ? vb[i] : va[i];

        uint32_t any = 0u;
#pragma unroll
        for (int i = 0; i < 4; i++)
            any |= __float_as_uint(vv[i].x) | __float_as_uint(vv[i].y) |
                   __float_as_uint(vv[i].z) | __float_as_uint(vv[i].w);

        if (any != 0u) {
            uint32_t* wb = s_buck[wid];
#pragma unroll
            for (int i = 0; i < 4; i++) {
                int j0 = (i * 256 + tid) * 4;
                uint32_t c0 = __float_as_uint(vv[i].x) | __float_as_uint(vv[i].y) |
                              __float_as_uint(vv[i].z) | __float_as_uint(vv[i].w);
                if (c0 != 0u) {
                    if (vv[i].x != 0.0f) atomicAdd(&wb[s_mtab[j0    ]], ((uint32_t)(j0    ) << 12) + 1u);
                    if (vv[i].y != 0.0f) atomicAdd(&wb[s_mtab[j0 + 1]], ((uint32_t)(j0 + 1) << 12) + 1u);
                    if (vv[i].z != 0.0f) atomicAdd(&wb[s_mtab[j0 + 2]], ((uint32_t)(j0 + 2) << 12) + 1u);
                    if (vv[i].w != 0.0f) atomicAdd(&wb[s_mtab[j0 + 3]], ((uint32_t)(j0 + 3) << 12) + 1u);
                }
            }
        }
        __syncthreads();

        if (tid < 17) {
            uint32_t s = s_buck[0][tid] + s_buck[1][tid] + s_buck[2][tid] + s_buck[3][tid] +
                         s_buck[4][tid] + s_buck[5][tid] + s_buck[6][tid] + s_buck[7][tid];
            s_tot[tid] = s;
        }
        __syncthreads();
        if (tid == 0) {
            float ss = 0.0f; int sc = 0;
            s_sufS[17] = 0.0f; s_sufC[17] = 0;
#pragma unroll
            for (int m = 16; m >= 0; m--) {
                uint32_t p = s_tot[m];
                ss += (float)(p >> 12);
                sc += (int)(p & 0xFFFu);
                s_sufS[m] = ss; s_sufC[m] = sc;
            }
        }
        __syncthreads();
        if (tid < 16) {
            int c = g_ck[tid];
            float sumA; int cntA;
            if (g_dirk[tid] == 0) { sumA = s_sufS[c];             cntA = s_sufC[c]; }
            else                  { sumA = s_sufS[0] - s_sufS[c]; cntA = s_sufC[0] - s_sufC[c]; }
            s_fin[tid] = w1[tid] * sumA + b1[tid] * (float)cntA;
        }
        __syncthreads();

        const float cntf = (float)s_sufC[0];
        float val = cntf * b2[tid];
#pragma unroll
        for (int k = 0; k < 16; k++) val = fmaf(s_fin[k], w2[k * DD + tid], val);
        g_h[(size_t)(row0 + r) * DD + tid] = to_tf32(val / fmaxf(cntf, 1.0f));
        __syncthreads();   // protect s_buck/s_fin before next iteration
    }
}

// ---------------- CSR build ----------------
__global__ void count_kernel(const int* __restrict__ col) {
    int e = blockIdx.x * blockDim.x + threadIdx.x;
    if (e < EE) atomicAdd(&g_cnt[col[e]], 1);
}

__global__ void scan_kernel() {
    __shared__ int s_w[32];
    __shared__ int s_carry;
    const int tid = threadIdx.x, lane = tid & 31, wid = tid >> 5;
    if (tid == 0) s_carry = 0;
    __syncthreads();
    for (int base = 0; base < NN; base += 1024) {
        int i = base + tid;
        int v = (i < NN) ? g_cnt[i] : 0;
        int x = v;
#pragma unroll
        for (int off = 1; off < 32; off <<= 1) {
            int t = __shfl_up_sync(0xffffffffu, x, off);
            if (lane >= off) x += t;
        }
        if (lane == 31) s_w[wid] = x;
        __syncthreads();
        if (tid < 32) {
            int y = s_w[tid];
#pragma unroll
            for (int off = 1; off < 32; off <<= 1) {
                int t = __shfl_up_sync(0xffffffffu, y, off);
                if (lane >= off) y += t;
            }
            s_w[tid] = y;
        }
        __syncthreads();
        int carry = s_carry;
        int pre = (wid > 0) ? s_w[wid - 1] : 0;
        int excl = carry + pre + x - v;
        if (i < NN) { g_off[i] = excl; g_cur[i] = excl; }
        __syncthreads();
        if (tid == 0) s_carry = carry + s_w[31];
        __syncthreads();
    }
    if (tid == 0) g_off[NN] = s_carry;
}

// =====================================================================
// transpose W (blocks 0..63) + scatter edges (blocks 64..2563)
// =====================================================================
__global__ void scatter_transpose_kernel(const int* __restrict__ row, const int* __restrict__ col,
                                         const float* __restrict__ attr,
                                         const float* __restrict__ W) {
    const int tid = threadIdx.x;
    if (blockIdx.x < 64) {
        __shared__ float t[32][33];
        const int bx = blockIdx.x & 7;
        const int by = blockIdx.x >> 3;
        const int lx = tid & 31, ly = tid >> 5;
#pragma unroll
        for (int r = 0; r < 4; r++)
            t[ly + r * 8][lx] = to_tf32(W[(bx * 32 + ly + r * 8) * DD + by * 32 + lx]);
        __syncthreads();
#pragma unroll
        for (int r = 0; r < 4; r++)
            g_wt[(by * 32 + ly + r * 8) * DD + bx * 32 + lx] = t[lx][ly + r * 8];
        return;
    }
    int e = (blockIdx.x - 64) * 256 + tid;
    if (e >= EE) return;
    int c = col[e];
    int p = atomicAdd(&g_cur[c], 1);
    g_edge[p] = make_int2(row[e], __float_as_int(attr[e]));
}

// =====================================================================
// tf32 mma.sync GEMM, cp.async double-buffered (BM=BN=128, BK=32)
// =====================================================================
#define ASTR 36
#define TILE_F (128 * ASTR)
#define BUF_BYTES (2 * TILE_F * 4)
#define SMEM_GEMM_TOTAL (2 * BUF_BYTES)     // 73728

__global__ __launch_bounds__(256, 2) void mma_gemm_kernel() {
    extern __shared__ float smem[];
    const int tid = threadIdx.x;
    const int lane = tid & 31;
    const int wid = tid >> 5;
    const int g = lane >> 2, t = lane & 3;
    const int wm = (wid & 1) * 64;
    const int wn = (wid >> 1) * 32;
    const int bn = blockIdx.x * 128;
    const int bm = blockIdx.y * 128;

    const uint32_t sbase = smem_u32(smem);
    const float* Ab = g_h + (size_t)bm * DD;
    const float* Bb = g_wt + (size_t)bn * DD;

    float acc[4][4][4];
#pragma unroll
    for (int i = 0; i < 4; i++)
#pragma unroll
        for (int j = 0; j < 4; j++)
#pragma unroll
            for (int c = 0; c < 4; c++) acc[i][j][c] = 0.0f;

    auto issue = [&](int c, int buf) {
        const uint32_t sa = sbase + buf * BUF_BYTES;
        const uint32_t sb = sa + TILE_F * 4;
        const int k0 = c * 32;
#pragma unroll
        for (int i = 0; i < 4; i++) {
            int task = tid + i * 256;
            int r = task >> 3, q = task & 7;
            CP_ASYNC16(sa + (uint32_t)(r * ASTR + q * 4) * 4,
                       (const char*)(Ab + (size_t)r * DD + k0 + q * 4));
        }
#pragma unroll
        for (int i = 0; i < 4; i++) {
            int task = tid + i * 256;
            int r = task >> 3, q = task & 7;
            CP_ASYNC16(sb + (uint32_t)(r * ASTR + q * 4) * 4,
                       (const char*)(Bb + (size_t)r * DD + k0 + q * 4));
        }
        CP_COMMIT();
    };

    issue(0, 0);

    for (int c = 0; c < 8; c++) {
        __syncthreads();
        if (c < 7) issue(c + 1, (c + 1) & 1);
        if (c < 7) { CP_WAIT(1); } else { CP_WAIT(0); }
        __syncthreads();

        const float* Asp = smem + (c & 1) * (BUF_BYTES / 4);
        const float* Bsp = Asp + TILE_F;
#pragma unroll
        for (int ks = 0; ks < 4; ks++) {
            const int kb = ks * 8;
            uint32_t bf[4][2];
#pragma unroll
            for (int nt = 0; nt < 4; nt++) {
                const float* bp = Bsp + (wn + nt * 8 + g) * ASTR + kb + t;
                bf[nt][0] = __float_as_uint(bp[0]);
                bf[nt][1] = __float_as_uint(bp[4]);
            }
#pragma unroll
            for (int mt = 0; mt < 4; mt++) {
                const int m0 = wm + mt * 16;
                const float* ap0 = Asp + (m0 + g) * ASTR + kb + t;
                const float* ap1 = Asp + (m0 + g + 8) * ASTR + kb + t;
                uint32_t af[4];
                af[0] = __float_as_uint(ap0[0]);
                af[1] = __float_as_uint(ap1[0]);
                af[2] = __float_as_uint(ap0[4]);
                af[3] = __float_as_uint(ap1[4]);
#pragma unroll
                for (int nt = 0; nt < 4; nt++)
                    mma_tf32(acc[mt][nt], af, bf[nt]);
            }
        }
    }

#pragma unroll
    for (int mt = 0; mt < 4; mt++) {
#pragma unroll
        for (int nt = 0; nt < 4; nt++) {
            const int r0 = bm + wm + mt * 16 + g;
            const int c0 = bn + wn + nt * 8 + 2 * t;
            *(float2*)(g_tmp + (size_t)r0 * DD + c0) =
                make_float2(acc[mt][nt][0], acc[mt][nt][1]);
            *(float2*)(g_tmp + (size_t)(r0 + 8) * DD + c0) =
                make_float2(acc[mt][nt][2], acc[mt][nt][3]);
        }
    }
}

// =====================================================================
// agg v3: float4 gathers, 4 groups-of-64 process 4 edges concurrently
// =====================================================================
__global__ __launch_bounds__(256) void agg_kernel(float* __restrict__ dst_out) {
    __shared__ float4 s_red4[4][64];
    const int c = blockIdx.x;
    const int tid = threadIdx.x;
    const int grp = tid >> 6, t64 = tid & 63;
    const int rs = __ldg(&g_off[c]), re = __ldg(&g_off[c + 1]);
    const float4* __restrict__ tmp4 = (const float4*)g_tmp;

    float4 acc = make_float4(0.0f, 0.0f, 0.0f, 0.0f);
    int e = rs + grp;
    for (; e + 4 < re; e += 8) {
        int2 e0 = __ldg(&g_edge[e]);
        int2 e1 = __ldg(&g_edge[e + 4]);
        float4 v0 = __ldg(&tmp4[(size_t)e0.x * 64 + t64]);
        float4 v1 = __ldg(&tmp4[(size_t)e1.x * 64 + t64]);
        float a0 = __int_as_float(e0.y), a1 = __int_as_float(e1.y);
        acc.x = fmaf(a0, v0.x, acc.x);
        acc.y = fmaf(a0, v0.y, acc.y);
        acc.z = fmaf(a0, v0.z, acc.z);
        acc.w = fmaf(a0, v0.w, acc.w);
        acc.x = fmaf(a1, v1.x, acc.x);
        acc.y = fmaf(a1, v1.y, acc.y);
        acc.z = fmaf(a1, v1.z, acc.z);
        acc.w = fmaf(a1, v1.w, acc.w);
    }
    if (e < re) {
        int2 e0 = __ldg(&g_edge[e]);
        float4 v0 = __ldg(&tmp4[(size_t)e0.x * 64 + t64]);
        float a0 = __int_as_float(e0.y);
        acc.x = fmaf(a0, v0.x, acc.x);
        acc.y = fmaf(a0, v0.y, acc.y);
        acc.z = fmaf(a0, v0.z, acc.z);
        acc.w = fmaf(a0, v0.w, acc.w);
    }
    s_red4[grp][t64] = acc;
    __syncthreads();

    const float* sr = (const float*)s_red4;
    float r = sr[tid] + sr[256 + tid] + sr[512 + tid] + sr[768 + tid];
    r = fmaxf(r, 0.0f);
    if (dst_out) dst_out[(size_t)c * DD + tid] = r;
    else         g_h[(size_t)c * DD + tid] = to_tf32(r);
}

// ---------------- launch ----------------
extern "C" void kernel_launch(void* const* d_in, const int* in_sizes, int n_in,
                              void* d_out, int out_size) {
    const float* init = (const float*)d_in[0];
    const int*   ei   = (const int*)d_in[1];
    const float* attr = (const float*)d_in[2];
    const float* w1   = (const float*)d_in[3];
    const float* b1   = (const float*)d_in[4];
    const float* w2   = (const float*)d_in[5];
    const float* b2   = (const float*)d_in[6];
    const float* W    = (const float*)d_in[7];
    float* out = (float*)d_out;

    const int* row = ei;
    const int* col = ei + EE;

    cudaFuncSetAttribute(mma_gemm_kernel, cudaFuncAttributeMaxDynamicSharedMemorySize,
                         SMEM_GEMM_TOTAL);

    prep_zero_kernel<<<80, 256>>>(w1, b1);                        // 0
    count_kernel<<<(EE + 255) / 256, 256>>>(col);                 // 1
    scan_kernel<<<1, 1024>>>();                                   // 2
    row_embed_kernel<<<NN / 2, 256>>>(init, w1, b1, w2, b2);      // 3 <- ncu slot
    scatter_transpose_kernel<<<64 + (EE + 255) / 256, 256>>>(row, col, attr, W);  // 4

    dim3 gemm_grid(DD / 128, M_PAD / 128);
    for (int layer = 0; layer < 3; layer++) {
        mma_gemm_kernel<<<gemm_grid, 256, SMEM_GEMM_TOTAL>>>();
        agg_kernel<<<NN, 256>>>(layer == 2 ? out : nullptr);
    }
}

// round 12
// speedup vs baseline: 1.1077x; 1.1077x over previous
#include <cuda_runtime.h>
#include <cuda_bf16.h>
#include <cstdint>

#define NN 20000
#define SS 4096
#define EE 640000
#define DD 256
#define M_PAD 20096   // 157 * 128

// ---------------- scratch (zero-initialized device globals) ----------------
__device__ float g_h[M_PAD * DD];          // current node features (tf32-rounded)
__device__ float g_tmp[M_PAD * DD];        // h @ W
__device__ float g_wt[DD * DD];            // W^T (K-major), tf32-rounded
__device__ int   g_cnt[NN];
__device__ int   g_off[NN + 1];
__device__ int   g_cur[NN];
__device__ int2  g_edge[EE];               // packed (src_row, attr_bits), CSR order
// embed closed-form tables
__device__ __align__(16) unsigned char g_mtab[SS];  // j -> interval index (0..16)
__device__ int g_ck[16];                            // rank per k
__device__ int g_dirk[16];                          // 0 = suffix active, 1 = prefix active

// ---------------- helpers ----------------
__device__ __forceinline__ uint32_t smem_u32(const void* p) {
    uint32_t a;
    asm("{ .reg .u64 t; cvta.to.shared.u64 t, %1; cvt.u32.u64 %0, t; }" : "=r"(a) : "l"(p));
    return a;
}
__device__ __forceinline__ float to_tf32(float x) {
    uint32_t u;
    asm("cvt.rna.tf32.f32 %0, %1;" : "=r"(u) : "f"(x));
    return __uint_as_float(u);
}
#define CP_ASYNC16(s, g) asm volatile("cp.async.cg.shared.global [%0], [%1], 16;" :: "r"(s), "l"(g) : "memory")
#define CP_COMMIT()      asm volatile("cp.async.commit_group;" ::: "memory")
#define CP_WAIT(n)       asm volatile("cp.async.wait_group %0;" :: "n"(n) : "memory")

__device__ __forceinline__ void mma_tf32(float* d, const uint32_t* a, const uint32_t* b) {
    asm volatile(
        "mma.sync.aligned.m16n8k8.row.col.f32.tf32.tf32.f32 "
        "{%0,%1,%2,%3}, {%4,%5,%6,%7}, {%8,%9}, {%0,%1,%2,%3};"
        : "+f"(d[0]), "+f"(d[1]), "+f"(d[2]), "+f"(d[3])
        : "r"(a[0]), "r"(a[1]), "r"(a[2]), "r"(a[3]), "r"(b[0]), "r"(b[1]));
}

// =====================================================================
// prep (block 0) + zero_counts (blocks 1..79)
// =====================================================================
__global__ void prep_zero_kernel(const float* __restrict__ w1, const float* __restrict__ b1) {
    const int tid = threadIdx.x;
    if (blockIdx.x != 0) {
        int i = (blockIdx.x - 1) * 256 + tid;
        if (i < NN) g_cnt[i] = 0;
        return;
    }
    __shared__ int s_B[16];
    __shared__ int s_bnd[16];
    if (tid < 16) {
        float w = w1[tid], b = b1[tid];
        int B, dir;
        if (w > 0.0f) {
            float t = -b / w;
            int cand = (int)floorf(t) - 1;
            if (cand < 0) cand = 0;
            if (cand > SS) cand = SS;
            while (cand < SS && !(fmaf((float)cand, w, b) > 0.0f)) cand++;
            B = cand; dir = 0;
        } else if (w < 0.0f) {
            float t = -b / w;
            int cand = (int)floorf(t) - 1;
            if (cand < 0) cand = 0;
            if (cand > SS) cand = SS;
            while (cand < SS && (fmaf((float)cand, w, b) > 0.0f)) cand++;
            B = cand; dir = 1;
        } else {
            if (b > 0.0f) { B = 0; dir = 0; }
            else          { B = 0; dir = 1; }
        }
        s_B[tid] = B;
        g_dirk[tid] = dir;
    }
    __syncthreads();
    if (tid < 16) {
        int Bk = s_B[tid], pos = 0;
#pragma unroll
        for (int i = 0; i < 16; i++) {
            int Bi = s_B[i];
            if (Bi < Bk || (Bi == Bk && i < tid)) pos++;
        }
        s_bnd[pos] = Bk;
    }
    __syncthreads();
    if (tid < 16) {
        int Bk = s_B[tid], c = 0;
#pragma unroll
        for (int i = 0; i < 16; i++) c += (s_bnd[i] <= Bk) ? 1 : 0;
        g_ck[tid] = c;
    }
    for (int j = tid; j < SS; j += blockDim.x) {
        int m = 0;
#pragma unroll
        for (int i = 0; i < 16; i++) m += (s_bnd[i] <= j) ? 1 : 0;
        g_mtab[j] = (unsigned char)m;
    }
}

// =====================================================================
// Row embedding v3: zero-skip (64B OR-tree) + per-warp bucket atomics
// (1 row/block — measured optimum: 32 regs, ~94% occ, ~67us)
// =====================================================================
__global__ __launch_bounds__(256) void row_embed_kernel(
        const float* __restrict__ init,
        const float* __restrict__ w1, const float* __restrict__ b1,
        const float* __restrict__ w2, const float* __restrict__ b2) {
    __shared__ unsigned char s_mtab[SS];
    __shared__ uint32_t s_buck[8][17];     // per-warp packed (sum<<12 | cnt)
    __shared__ float s_sufS[18];
    __shared__ int   s_sufC[18];
    __shared__ float s_fin[16];
    const int row = blockIdx.x;
    const int tid = threadIdx.x;
    const int wid = tid >> 5;

    ((uint4*)s_mtab)[tid] = ((const uint4*)g_mtab)[tid];
    if (tid < 136) ((uint32_t*)s_buck)[tid] = 0u;
    __syncthreads();

    const float4* rp = (const float4*)(init + (size_t)row * SS);
    float4 v0 = rp[tid];
    float4 v1 = rp[256 + tid];
    float4 v2 = rp[512 + tid];
    float4 v3 = rp[768 + tid];

    uint32_t any =
        (__float_as_uint(v0.x) | __float_as_uint(v0.y) | __float_as_uint(v0.z) | __float_as_uint(v0.w)) |
        (__float_as_uint(v1.x) | __float_as_uint(v1.y) | __float_as_uint(v1.z) | __float_as_uint(v1.w)) |
        (__float_as_uint(v2.x) | __float_as_uint(v2.y) | __float_as_uint(v2.z) | __float_as_uint(v2.w)) |
        (__float_as_uint(v3.x) | __float_as_uint(v3.y) | __float_as_uint(v3.z) | __float_as_uint(v3.w));

    if (any != 0u) {
        uint32_t* wb = s_buck[wid];
        float4 vv[4] = {v0, v1, v2, v3};
#pragma unroll
        for (int i = 0; i < 4; i++) {
            int j0 = (i * 256 + tid) * 4;
            uint32_t c0 = __float_as_uint(vv[i].x) | __float_as_uint(vv[i].y) |
                          __float_as_uint(vv[i].z) | __float_as_uint(vv[i].w);
            if (c0 != 0u) {
                if (vv[i].x != 0.0f) atomicAdd(&wb[s_mtab[j0    ]], ((uint32_t)(j0    ) << 12) + 1u);
                if (vv[i].y != 0.0f) atomicAdd(&wb[s_mtab[j0 + 1]], ((uint32_t)(j0 + 1) << 12) + 1u);
                if (vv[i].z != 0.0f) atomicAdd(&wb[s_mtab[j0 + 2]], ((uint32_t)(j0 + 2) << 12) + 1u);
                if (vv[i].w != 0.0f) atomicAdd(&wb[s_mtab[j0 + 3]], ((uint32_t)(j0 + 3) << 12) + 1u);
            }
        }
    }
    __syncthreads();

    if (tid == 0) {
        float ss = 0.0f; int sc = 0;
        s_sufS[17] = 0.0f; s_sufC[17] = 0;
        for (int m = 16; m >= 0; m--) {
            uint32_t p = s_buck[0][m] + s_buck[1][m] + s_buck[2][m] + s_buck[3][m] +
                         s_buck[4][m] + s_buck[5][m] + s_buck[6][m] + s_buck[7][m];
            ss += (float)(p >> 12);
            sc += (int)(p & 0xFFFu);
            s_sufS[m] = ss; s_sufC[m] = sc;
        }
    }
    __syncthreads();
    if (tid < 16) {
        int c = g_ck[tid];
        float sumA; int cntA;
        if (g_dirk[tid] == 0) { sumA = s_sufS[c];             cntA = s_sufC[c]; }
        else                  { sumA = s_sufS[0] - s_sufS[c]; cntA = s_sufC[0] - s_sufC[c]; }
        s_fin[tid] = w1[tid] * sumA + b1[tid] * (float)cntA;
    }
    __syncthreads();

    const float cntf = (float)s_sufC[0];
    float val = cntf * b2[tid];
#pragma unroll
    for (int k = 0; k < 16; k++) val = fmaf(s_fin[k], w2[k * DD + tid], val);
    g_h[(size_t)row * DD + tid] = to_tf32(val / fmaxf(cntf, 1.0f));
}

// ---------------- CSR build ----------------
__global__ void count_kernel(const int* __restrict__ col) {
    int e = blockIdx.x * blockDim.x + threadIdx.x;
    if (e < EE) atomicAdd(&g_cnt[col[e]], 1);
}

__global__ void scan_kernel() {
    __shared__ int s_w[32];
    __shared__ int s_carry;
    const int tid = threadIdx.x, lane = tid & 31, wid = tid >> 5;
    if (tid == 0) s_carry = 0;
    __syncthreads();
    for (int base = 0; base < NN; base += 1024) {
        int i = base + tid;
        int v = (i < NN) ? g_cnt[i] : 0;
        int x = v;
#pragma unroll
        for (int off = 1; off < 32; off <<= 1) {
            int t = __shfl_up_sync(0xffffffffu, x, off);
            if (lane >= off) x += t;
        }
        if (lane == 31) s_w[wid] = x;
        __syncthreads();
        if (tid < 32) {
            int y = s_w[tid];
#pragma unroll
            for (int off = 1; off < 32; off <<= 1) {
                int t = __shfl_up_sync(0xffffffffu, y, off);
                if (lane >= off) y += t;
            }
            s_w[tid] = y;
        }
        __syncthreads();
        int carry = s_carry;
        int pre = (wid > 0) ? s_w[wid - 1] : 0;
        int excl = carry + pre + x - v;
        if (i < NN) { g_off[i] = excl; g_cur[i] = excl; }
        __syncthreads();
        if (tid == 0) s_carry = carry + s_w[31];
        __syncthreads();
    }
    if (tid == 0) g_off[NN] = s_carry;
}

// =====================================================================
// transpose W (blocks 0..63) + scatter edges (blocks 64..2563)
// =====================================================================
__global__ void scatter_transpose_kernel(const int* __restrict__ row, const int* __restrict__ col,
                                         const float* __restrict__ attr,
                                         const float* __restrict__ W) {
    const int tid = threadIdx.x;
    if (blockIdx.x < 64) {
        __shared__ float t[32][33];
        const int bx = blockIdx.x & 7;
        const int by = blockIdx.x >> 3;
        const int lx = tid & 31, ly = tid >> 5;
#pragma unroll
        for (int r = 0; r < 4; r++)
            t[ly + r * 8][lx] = to_tf32(W[(bx * 32 + ly + r * 8) * DD + by * 32 + lx]);
        __syncthreads();
#pragma unroll
        for (int r = 0; r < 4; r++)
            g_wt[(by * 32 + ly + r * 8) * DD + bx * 32 + lx] = t[lx][ly + r * 8];
        return;
    }
    int e = (blockIdx.x - 64) * 256 + tid;
    if (e >= EE) return;
    int c = col[e];
    int p = atomicAdd(&g_cur[c], 1);
    g_edge[p] = make_int2(row[e], __float_as_int(attr[e]));
}

// =====================================================================
// tf32 mma.sync GEMM, cp.async double-buffered (BM=BN=128, BK=32)
// =====================================================================
#define ASTR 36
#define TILE_F (128 * ASTR)
#define BUF_BYTES (2 * TILE_F * 4)
#define SMEM_GEMM_TOTAL (2 * BUF_BYTES)     // 73728

__global__ __launch_bounds__(256, 2) void mma_gemm_kernel() {
    extern __shared__ float smem[];
    const int tid = threadIdx.x;
    const int lane = tid & 31;
    const int wid = tid >> 5;
    const int g = lane >> 2, t = lane & 3;
    const int wm = (wid & 1) * 64;
    const int wn = (wid >> 1) * 32;
    const int bn = blockIdx.x * 128;
    const int bm = blockIdx.y * 128;

    const uint32_t sbase = smem_u32(smem);
    const float* Ab = g_h + (size_t)bm * DD;
    const float* Bb = g_wt + (size_t)bn * DD;

    float acc[4][4][4];
#pragma unroll
    for (int i = 0; i < 4; i++)
#pragma unroll
        for (int j = 0; j < 4; j++)
#pragma unroll
            for (int c = 0; c < 4; c++) acc[i][j][c] = 0.0f;

    auto issue = [&](int c, int buf) {
        const uint32_t sa = sbase + buf * BUF_BYTES;
        const uint32_t sb = sa + TILE_F * 4;
        const int k0 = c * 32;
#pragma unroll
        for (int i = 0; i < 4; i++) {
            int task = tid + i * 256;
            int r = task >> 3, q = task & 7;
            CP_ASYNC16(sa + (uint32_t)(r * ASTR + q * 4) * 4,
                       (const char*)(Ab + (size_t)r * DD + k0 + q * 4));
        }
#pragma unroll
        for (int i = 0; i < 4; i++) {
            int task = tid + i * 256;
            int r = task >> 3, q = task & 7;
            CP_ASYNC16(sb + (uint32_t)(r * ASTR + q * 4) * 4,
                       (const char*)(Bb + (size_t)r * DD + k0 + q * 4));
        }
        CP_COMMIT();
    };

    issue(0, 0);

    for (int c = 0; c < 8; c++) {
        __syncthreads();
        if (c < 7) issue(c + 1, (c + 1) & 1);
        if (c < 7) { CP_WAIT(1); } else { CP_WAIT(0); }
        __syncthreads();

        const float* Asp = smem + (c & 1) * (BUF_BYTES / 4);
        const float* Bsp = Asp + TILE_F;
#pragma unroll
        for (int ks = 0; ks < 4; ks++) {
            const int kb = ks * 8;
            uint32_t bf[4][2];
#pragma unroll
            for (int nt = 0; nt < 4; nt++) {
                const float* bp = Bsp + (wn + nt * 8 + g) * ASTR + kb + t;
                bf[nt][0] = __float_as_uint(bp[0]);
                bf[nt][1] = __float_as_uint(bp[4]);
            }
#pragma unroll
            for (int mt = 0; mt < 4; mt++) {
                const int m0 = wm + mt * 16;
                const float* ap0 = Asp + (m0 + g) * ASTR + kb + t;
                const float* ap1 = Asp + (m0 + g + 8) * ASTR + kb + t;
                uint32_t af[4];
                af[0] = __float_as_uint(ap0[0]);
                af[1] = __float_as_uint(ap1[0]);
                af[2] = __float_as_uint(ap0[4]);
                af[3] = __float_as_uint(ap1[4]);
#pragma unroll
                for (int nt = 0; nt < 4; nt++)
                    mma_tf32(acc[mt][nt], af, bf[nt]);
            }
        }
    }

#pragma unroll
    for (int mt = 0; mt < 4; mt++) {
#pragma unroll
        for (int nt = 0; nt < 4; nt++) {
            const int r0 = bm + wm + mt * 16 + g;
            const int c0 = bn + wn + nt * 8 + 2 * t;
            *(float2*)(g_tmp + (size_t)r0 * DD + c0) =
                make_float2(acc[mt][nt][0], acc[mt][nt][1]);
            *(float2*)(g_tmp + (size_t)(r0 + 8) * DD + c0) =
                make_float2(acc[mt][nt][2], acc[mt][nt][3]);
        }
    }
}

// =====================================================================
// agg v3: float4 gathers, 4 groups-of-64 process 4 edges concurrently
// =====================================================================
__global__ __launch_bounds__(256) void agg_kernel(float* __restrict__ dst_out) {
    __shared__ float4 s_red4[4][64];
    const int c = blockIdx.x;
    const int tid = threadIdx.x;
    const int grp = tid >> 6, t64 = tid & 63;
    const int rs = __ldg(&g_off[c]), re = __ldg(&g_off[c + 1]);
    const float4* __restrict__ tmp4 = (const float4*)g_tmp;

    float4 acc = make_float4(0.0f, 0.0f, 0.0f, 0.0f);
    int e = rs + grp;
    for (; e + 4 < re; e += 8) {
        int2 e0 = __ldg(&g_edge[e]);
        int2 e1 = __ldg(&g_edge[e + 4]);
        float4 v0 = __ldg(&tmp4[(size_t)e0.x * 64 + t64]);
        float4 v1 = __ldg(&tmp4[(size_t)e1.x * 64 + t64]);
        float a0 = __int_as_float(e0.y), a1 = __int_as_float(e1.y);
        acc.x = fmaf(a0, v0.x, acc.x);
        acc.y = fmaf(a0, v0.y, acc.y);
        acc.z = fmaf(a0, v0.z, acc.z);
        acc.w = fmaf(a0, v0.w, acc.w);
        acc.x = fmaf(a1, v1.x, acc.x);
        acc.y = fmaf(a1, v1.y, acc.y);
        acc.z = fmaf(a1, v1.z, acc.z);
        acc.w = fmaf(a1, v1.w, acc.w);
    }
    if (e < re) {
        int2 e0 = __ldg(&g_edge[e]);
        float4 v0 = __ldg(&tmp4[(size_t)e0.x * 64 + t64]);
        float a0 = __int_as_float(e0.y);
        acc.x = fmaf(a0, v0.x, acc.x);
        acc.y = fmaf(a0, v0.y, acc.y);
        acc.z = fmaf(a0, v0.z, acc.z);
        acc.w = fmaf(a0, v0.w, acc.w);
    }
    s_red4[grp][t64] = acc;
    __syncthreads();

    const float* sr = (const float*)s_red4;
    float r = sr[tid] + sr[256 + tid] + sr[512 + tid] + sr[768 + tid];
    r = fmaxf(r, 0.0f);
    if (dst_out) dst_out[(size_t)c * DD + tid] = r;
    else         g_h[(size_t)c * DD + tid] = to_tf32(r);
}

// ---------------- launch ----------------
extern "C" void kernel_launch(void* const* d_in, const int* in_sizes, int n_in,
                              void* d_out, int out_size) {
    const float* init = (const float*)d_in[0];
    const int*   ei   = (const int*)d_in[1];
    const float* attr = (const float*)d_in[2];
    const float* w1   = (const float*)d_in[3];
    const float* b1   = (const float*)d_in[4];
    const float* w2   = (const float*)d_in[5];
    const float* b2   = (const float*)d_in[6];
    const float* W    = (const float*)d_in[7];
    float* out = (float*)d_out;

    const int* row = ei;
    const int* col = ei + EE;

    cudaFuncSetAttribute(mma_gemm_kernel, cudaFuncAttributeMaxDynamicSharedMemorySize,
                         SMEM_GEMM_TOTAL);

    prep_zero_kernel<<<80, 256>>>(w1, b1);                        // 0
    count_kernel<<<(EE + 255) / 256, 256>>>(col);                 // 1
    scan_kernel<<<1, 1024>>>();                                   // 2
    row_embed_kernel<<<NN, 256>>>(init, w1, b1, w2, b2);          // 3 <- ncu slot (canary)
    scatter_transpose_kernel<<<64 + (EE + 255) / 256, 256>>>(row, col, attr, W);  // 4

    dim3 gemm_grid(DD / 128, M_PAD / 128);
    for (int layer = 0; layer < 3; layer++) {
        mma_gemm_kernel<<<gemm_grid, 256, SMEM_GEMM_TOTAL>>>();
        agg_kernel<<<NN, 256>>>(layer == 2 ? out : nullptr);
    }
}

// round 13
// speedup vs baseline: 1.1215x; 1.0125x over previous
#include <cuda_runtime.h>
#include <cuda_bf16.h>
#include <cstdint>

#define NN 20000
#define SS 4096
#define EE 640000
#define DD 256
#define M_PAD 20096   // 157 * 128

// ---------------- scratch (zero-initialized device globals) ----------------
__device__ float g_h[M_PAD * DD];          // current node features (tf32-rounded)
__device__ float g_tmp[M_PAD * DD];        // h @ W
__device__ float g_wt[DD * DD];            // W^T (K-major), tf32-rounded
__device__ int   g_cnt[NN];
__device__ int   g_off[NN + 1];
__device__ int   g_cur[NN];
__device__ int2  g_edge[EE];               // packed (src_row, attr_bits), CSR order
// embed closed-form tables
__device__ __align__(16) unsigned char g_mtab[SS];  // j -> interval index (0..16)
__device__ int g_ck[16];                            // rank per k
__device__ int g_dirk[16];                          // 0 = suffix active, 1 = prefix active

// ---------------- helpers ----------------
__device__ __forceinline__ uint32_t smem_u32(const void* p) {
    uint32_t a;
    asm("{ .reg .u64 t; cvta.to.shared.u64 t, %1; cvt.u32.u64 %0, t; }" : "=r"(a) : "l"(p));
    return a;
}
__device__ __forceinline__ float to_tf32(float x) {
    uint32_t u;
    asm("cvt.rna.tf32.f32 %0, %1;" : "=r"(u) : "f"(x));
    return __uint_as_float(u);
}
#define CP_ASYNC16(s, g) asm volatile("cp.async.cg.shared.global [%0], [%1], 16;" :: "r"(s), "l"(g) : "memory")
#define CP_COMMIT()      asm volatile("cp.async.commit_group;" ::: "memory")
#define CP_WAIT(n)       asm volatile("cp.async.wait_group %0;" :: "n"(n) : "memory")

__device__ __forceinline__ void mma_tf32(float* d, const uint32_t* a, const uint32_t* b) {
    asm volatile(
        "mma.sync.aligned.m16n8k8.row.col.f32.tf32.tf32.f32 "
        "{%0,%1,%2,%3}, {%4,%5,%6,%7}, {%8,%9}, {%0,%1,%2,%3};"
        : "+f"(d[0]), "+f"(d[1]), "+f"(d[2]), "+f"(d[3])
        : "r"(a[0]), "r"(a[1]), "r"(a[2]), "r"(a[3]), "r"(b[0]), "r"(b[1]));
}

// =====================================================================
// prep (block 0) + zero_counts (blocks 1..79)
// =====================================================================
__global__ void prep_zero_kernel(const float* __restrict__ w1, const float* __restrict__ b1) {
    const int tid = threadIdx.x;
    if (blockIdx.x != 0) {
        int i = (blockIdx.x - 1) * 256 + tid;
        if (i < NN) g_cnt[i] = 0;
        return;
    }
    __shared__ int s_B[16];
    __shared__ int s_bnd[16];
    if (tid < 16) {
        float w = w1[tid], b = b1[tid];
        int B, dir;
        if (w > 0.0f) {
            float t = -b / w;
            int cand = (int)floorf(t) - 1;
            if (cand < 0) cand = 0;
            if (cand > SS) cand = SS;
            while (cand < SS && !(fmaf((float)cand, w, b) > 0.0f)) cand++;
            B = cand; dir = 0;
        } else if (w < 0.0f) {
            float t = -b / w;
            int cand = (int)floorf(t) - 1;
            if (cand < 0) cand = 0;
            if (cand > SS) cand = SS;
            while (cand < SS && (fmaf((float)cand, w, b) > 0.0f)) cand++;
            B = cand; dir = 1;
        } else {
            if (b > 0.0f) { B = 0; dir = 0; }
            else          { B = 0; dir = 1; }
        }
        s_B[tid] = B;
        g_dirk[tid] = dir;
    }
    __syncthreads();
    if (tid < 16) {
        int Bk = s_B[tid], pos = 0;
#pragma unroll
        for (int i = 0; i < 16; i++) {
            int Bi = s_B[i];
            if (Bi < Bk || (Bi == Bk && i < tid)) pos++;
        }
        s_bnd[pos] = Bk;
    }
    __syncthreads();
    if (tid < 16) {
        int Bk = s_B[tid], c = 0;
#pragma unroll
        for (int i = 0; i < 16; i++) c += (s_bnd[i] <= Bk) ? 1 : 0;
        g_ck[tid] = c;
    }
    for (int j = tid; j < SS; j += blockDim.x) {
        int m = 0;
#pragma unroll
        for (int i = 0; i < 16; i++) m += (s_bnd[i] <= j) ? 1 : 0;
        g_mtab[j] = (unsigned char)m;
    }
}

// =====================================================================
// Row embedding v3: zero-skip (64B OR-tree) + per-warp bucket atomics
// =====================================================================
__global__ __launch_bounds__(256) void row_embed_kernel(
        const float* __restrict__ init,
        const float* __restrict__ w1, const float* __restrict__ b1,
        const float* __restrict__ w2, const float* __restrict__ b2) {
    __shared__ unsigned char s_mtab[SS];
    __shared__ uint32_t s_buck[8][17];     // per-warp packed (sum<<12 | cnt)
    __shared__ float s_sufS[18];
    __shared__ int   s_sufC[18];
    __shared__ float s_fin[16];
    const int row = blockIdx.x;
    const int tid = threadIdx.x;
    const int wid = tid >> 5;

    ((uint4*)s_mtab)[tid] = ((const uint4*)g_mtab)[tid];
    if (tid < 136) ((uint32_t*)s_buck)[tid] = 0u;
    __syncthreads();

    const float4* rp = (const float4*)(init + (size_t)row * SS);
    float4 v0 = rp[tid];
    float4 v1 = rp[256 + tid];
    float4 v2 = rp[512 + tid];
    float4 v3 = rp[768 + tid];

    uint32_t any =
        (__float_as_uint(v0.x) | __float_as_uint(v0.y) | __float_as_uint(v0.z) | __float_as_uint(v0.w)) |
        (__float_as_uint(v1.x) | __float_as_uint(v1.y) | __float_as_uint(v1.z) | __float_as_uint(v1.w)) |
        (__float_as_uint(v2.x) | __float_as_uint(v2.y) | __float_as_uint(v2.z) | __float_as_uint(v2.w)) |
        (__float_as_uint(v3.x) | __float_as_uint(v3.y) | __float_as_uint(v3.z) | __float_as_uint(v3.w));

    if (any != 0u) {
        uint32_t* wb = s_buck[wid];
        float4 vv[4] = {v0, v1, v2, v3};
#pragma unroll
        for (int i = 0; i < 4; i++) {
            int j0 = (i * 256 + tid) * 4;
            uint32_t c0 = __float_as_uint(vv[i].x) | __float_as_uint(vv[i].y) |
                          __float_as_uint(vv[i].z) | __float_as_uint(vv[i].w);
            if (c0 != 0u) {
                if (vv[i].x != 0.0f) atomicAdd(&wb[s_mtab[j0    ]], ((uint32_t)(j0    ) << 12) + 1u);
                if (vv[i].y != 0.0f) atomicAdd(&wb[s_mtab[j0 + 1]], ((uint32_t)(j0 + 1) << 12) + 1u);
                if (vv[i].z != 0.0f) atomicAdd(&wb[s_mtab[j0 + 2]], ((uint32_t)(j0 + 2) << 12) + 1u);
                if (vv[i].w != 0.0f) atomicAdd(&wb[s_mtab[j0 + 3]], ((uint32_t)(j0 + 3) << 12) + 1u);
            }
        }
    }
    __syncthreads();

    if (tid == 0) {
        float ss = 0.0f; int sc = 0;
        s_sufS[17] = 0.0f; s_sufC[17] = 0;
        for (int m = 16; m >= 0; m--) {
            uint32_t p = s_buck[0][m] + s_buck[1][m] + s_buck[2][m] + s_buck[3][m] +
                         s_buck[4][m] + s_buck[5][m] + s_buck[6][m] + s_buck[7][m];
            ss += (float)(p >> 12);
            sc += (int)(p & 0xFFFu);
            s_sufS[m] = ss; s_sufC[m] = sc;
        }
    }
    __syncthreads();
    if (tid < 16) {
        int c = g_ck[tid];
        float sumA; int cntA;
        if (g_dirk[tid] == 0) { sumA = s_sufS[c];             cntA = s_sufC[c]; }
        else                  { sumA = s_sufS[0] - s_sufS[c]; cntA = s_sufC[0] - s_sufC[c]; }
        s_fin[tid] = w1[tid] * sumA + b1[tid] * (float)cntA;
    }
    __syncthreads();

    const float cntf = (float)s_sufC[0];
    float val = cntf * b2[tid];
#pragma unroll
    for (int k = 0; k < 16; k++) val = fmaf(s_fin[k], w2[k * DD + tid], val);
    g_h[(size_t)row * DD + tid] = to_tf32(val / fmaxf(cntf, 1.0f));
}

// ---------------- CSR build ----------------
__global__ void count_kernel(const int* __restrict__ col) {
    int e = blockIdx.x * blockDim.x + threadIdx.x;
    if (e < EE) atomicAdd(&g_cnt[col[e]], 1);
}

__global__ void scan_kernel() {
    __shared__ int s_w[32];
    __shared__ int s_carry;
    const int tid = threadIdx.x, lane = tid & 31, wid = tid >> 5;
    if (tid == 0) s_carry = 0;
    __syncthreads();
    for (int base = 0; base < NN; base += 1024) {
        int i = base + tid;
        int v = (i < NN) ? g_cnt[i] : 0;
        int x = v;
#pragma unroll
        for (int off = 1; off < 32; off <<= 1) {
            int t = __shfl_up_sync(0xffffffffu, x, off);
            if (lane >= off) x += t;
        }
        if (lane == 31) s_w[wid] = x;
        __syncthreads();
        if (tid < 32) {
            int y = s_w[tid];
#pragma unroll
            for (int off = 1; off < 32; off <<= 1) {
                int t = __shfl_up_sync(0xffffffffu, y, off);
                if (lane >= off) y += t;
            }
            s_w[tid] = y;
        }
        __syncthreads();
        int carry = s_carry;
        int pre = (wid > 0) ? s_w[wid - 1] : 0;
        int excl = carry + pre + x - v;
        if (i < NN) { g_off[i] = excl; g_cur[i] = excl; }
        __syncthreads();
        if (tid == 0) s_carry = carry + s_w[31];
        __syncthreads();
    }
    if (tid == 0) g_off[NN] = s_carry;
}

// =====================================================================
// transpose W (blocks 0..63) + scatter edges (blocks 64..2563)
// =====================================================================
__global__ void scatter_transpose_kernel(const int* __restrict__ row, const int* __restrict__ col,
                                         const float* __restrict__ attr,
                                         const float* __restrict__ W) {
    const int tid = threadIdx.x;
    if (blockIdx.x < 64) {
        __shared__ float t[32][33];
        const int bx = blockIdx.x & 7;
        const int by = blockIdx.x >> 3;
        const int lx = tid & 31, ly = tid >> 5;
#pragma unroll
        for (int r = 0; r < 4; r++)
            t[ly + r * 8][lx] = to_tf32(W[(bx * 32 + ly + r * 8) * DD + by * 32 + lx]);
        __syncthreads();
#pragma unroll
        for (int r = 0; r < 4; r++)
            g_wt[(by * 32 + ly + r * 8) * DD + bx * 32 + lx] = t[lx][ly + r * 8];
        return;
    }
    int e = (blockIdx.x - 64) * 256 + tid;
    if (e >= EE) return;
    int c = col[e];
    int p = atomicAdd(&g_cur[c], 1);
    g_edge[p] = make_int2(row[e], __float_as_int(attr[e]));
}

// =====================================================================
// tf32 mma.sync GEMM, cp.async double-buffered (BM=BN=128, BK=32)
// =====================================================================
#define ASTR 36
#define TILE_F (128 * ASTR)
#define BUF_BYTES (2 * TILE_F * 4)
#define SMEM_GEMM_TOTAL (2 * BUF_BYTES)     // 73728

__global__ __launch_bounds__(256, 2) void mma_gemm_kernel() {
    extern __shared__ float smem[];
    const int tid = threadIdx.x;
    const int lane = tid & 31;
    const int wid = tid >> 5;
    const int g = lane >> 2, t = lane & 3;
    const int wm = (wid & 1) * 64;
    const int wn = (wid >> 1) * 32;
    const int bn = blockIdx.x * 128;
    const int bm = blockIdx.y * 128;

    const uint32_t sbase = smem_u32(smem);
    const float* Ab = g_h + (size_t)bm * DD;
    const float* Bb = g_wt + (size_t)bn * DD;

    float acc[4][4][4];
#pragma unroll
    for (int i = 0; i < 4; i++)
#pragma unroll
        for (int j = 0; j < 4; j++)
#pragma unroll
            for (int c = 0; c < 4; c++) acc[i][j][c] = 0.0f;

    auto issue = [&](int c, int buf) {
        const uint32_t sa = sbase + buf * BUF_BYTES;
        const uint32_t sb = sa + TILE_F * 4;
        const int k0 = c * 32;
#pragma unroll
        for (int i = 0; i < 4; i++) {
            int task = tid + i * 256;
            int r = task >> 3, q = task & 7;
            CP_ASYNC16(sa + (uint32_t)(r * ASTR + q * 4) * 4,
                       (const char*)(Ab + (size_t)r * DD + k0 + q * 4));
        }
#pragma unroll
        for (int i = 0; i < 4; i++) {
            int task = tid + i * 256;
            int r = task >> 3, q = task & 7;
            CP_ASYNC16(sb + (uint32_t)(r * ASTR + q * 4) * 4,
                       (const char*)(Bb + (size_t)r * DD + k0 + q * 4));
        }
        CP_COMMIT();
    };

    issue(0, 0);

    for (int c = 0; c < 8; c++) {
        __syncthreads();
        if (c < 7) issue(c + 1, (c + 1) & 1);
        if (c < 7) { CP_WAIT(1); } else { CP_WAIT(0); }
        __syncthreads();

        const float* Asp = smem + (c & 1) * (BUF_BYTES / 4);
        const float* Bsp = Asp + TILE_F;
#pragma unroll
        for (int ks = 0; ks < 4; ks++) {
            const int kb = ks * 8;
            uint32_t bf[4][2];
#pragma unroll
            for (int nt = 0; nt < 4; nt++) {
                const float* bp = Bsp + (wn + nt * 8 + g) * ASTR + kb + t;
                bf[nt][0] = __float_as_uint(bp[0]);
                bf[nt][1] = __float_as_uint(bp[4]);
            }
#pragma unroll
            for (int mt = 0; mt < 4; mt++) {
                const int m0 = wm + mt * 16;
                const float* ap0 = Asp + (m0 + g) * ASTR + kb + t;
                const float* ap1 = Asp + (m0 + g + 8) * ASTR + kb + t;
                uint32_t af[4];
                af[0] = __float_as_uint(ap0[0]);
                af[1] = __float_as_uint(ap1[0]);
                af[2] = __float_as_uint(ap0[4]);
                af[3] = __float_as_uint(ap1[4]);
#pragma unroll
                for (int nt = 0; nt < 4; nt++)
                    mma_tf32(acc[mt][nt], af, bf[nt]);
            }
        }
    }

#pragma unroll
    for (int mt = 0; mt < 4; mt++) {
#pragma unroll
        for (int nt = 0; nt < 4; nt++) {
            const int r0 = bm + wm + mt * 16 + g;
            const int c0 = bn + wn + nt * 8 + 2 * t;
            *(float2*)(g_tmp + (size_t)r0 * DD + c0) =
                make_float2(acc[mt][nt][0], acc[mt][nt][1]);
            *(float2*)(g_tmp + (size_t)(r0 + 8) * DD + c0) =
                make_float2(acc[mt][nt][2], acc[mt][nt][3]);
        }
    }
}

// =====================================================================
// agg v3: float4 gathers, 4 groups-of-64 process 4 edges concurrently
// =====================================================================
__global__ __launch_bounds__(256) void agg_kernel(float* __restrict__ dst_out) {
    __shared__ float4 s_red4[4][64];
    const int c = blockIdx.x;
    const int tid = threadIdx.x;
    const int grp = tid >> 6, t64 = tid & 63;
    const int rs = __ldg(&g_off[c]), re = __ldg(&g_off[c + 1]);
    const float4* __restrict__ tmp4 = (const float4*)g_tmp;

    float4 acc = make_float4(0.0f, 0.0f, 0.0f, 0.0f);
    int e = rs + grp;
    for (; e + 4 < re; e += 8) {
        int2 e0 = __ldg(&g_edge[e]);
        int2 e1 = __ldg(&g_edge[e + 4]);
        float4 v0 = __ldg(&tmp4[(size_t)e0.x * 64 + t64]);
        float4 v1 = __ldg(&tmp4[(size_t)e1.x * 64 + t64]);
        float a0 = __int_as_float(e0.y), a1 = __int_as_float(e1.y);
        acc.x = fmaf(a0, v0.x, acc.x);
        acc.y = fmaf(a0, v0.y, acc.y);
        acc.z = fmaf(a0, v0.z, acc.z);
        acc.w = fmaf(a0, v0.w, acc.w);
        acc.x = fmaf(a1, v1.x, acc.x);
        acc.y = fmaf(a1, v1.y, acc.y);
        acc.z = fmaf(a1, v1.z, acc.z);
        acc.w = fmaf(a1, v1.w, acc.w);
    }
    if (e < re) {
        int2 e0 = __ldg(&g_edge[e]);
        float4 v0 = __ldg(&tmp4[(size_t)e0.x * 64 + t64]);
        float a0 = __int_as_float(e0.y);
        acc.x = fmaf(a0, v0.x, acc.x);
        acc.y = fmaf(a0, v0.y, acc.y);
        acc.z = fmaf(a0, v0.z, acc.z);
        acc.w = fmaf(a0, v0.w, acc.w);
    }
    s_red4[grp][t64] = acc;
    __syncthreads();

    const float* sr = (const float*)s_red4;
    float r = sr[tid] + sr[256 + tid] + sr[512 + tid] + sr[768 + tid];
    r = fmaxf(r, 0.0f);
    if (dst_out) dst_out[(size_t)c * DD + tid] = r;
    else         g_h[(size_t)c * DD + tid] = to_tf32(r);
}

// ---------------- launch ----------------
extern "C" void kernel_launch(void* const* d_in, const int* in_sizes, int n_in,
                              void* d_out, int out_size) {
    const float* init = (const float*)d_in[0];
    const int*   ei   = (const int*)d_in[1];
    const float* attr = (const float*)d_in[2];
    const float* w1   = (const float*)d_in[3];
    const float* b1   = (const float*)d_in[4];
    const float* w2   = (const float*)d_in[5];
    const float* b2   = (const float*)d_in[6];
    const float* W    = (const float*)d_in[7];
    float* out = (float*)d_out;

    const int* row = ei;
    const int* col = ei + EE;

    cudaFuncSetAttribute(mma_gemm_kernel, cudaFuncAttributeMaxDynamicSharedMemorySize,
                         SMEM_GEMM_TOTAL);

    // Fork-join: embed runs on a side stream concurrently with the CSR chain.
    // Streams/events are created per call and intentionally NOT destroyed
    // (destroying a capture-participating stream before EndCapture would
    // invalidate capture). Host-side objects only — no device allocation.
    cudaStream_t s2;
    cudaStreamCreateWithFlags(&s2, cudaStreamNonBlocking);
    cudaEvent_t evA, evB;
    cudaEventCreateWithFlags(&evA, cudaEventDisableTiming);
    cudaEventCreateWithFlags(&evB, cudaEventDisableTiming);

    prep_zero_kernel<<<80, 256>>>(w1, b1);                        // 0 (main)
    cudaEventRecord(evA, 0);

    count_kernel<<<(EE + 255) / 256, 256>>>(col);                 // 1 (main)
    scan_kernel<<<1, 1024>>>();                                   // 2 (main)

    cudaStreamWaitEvent(s2, evA, 0);
    row_embed_kernel<<<NN, 256, 0, s2>>>(init, w1, b1, w2, b2);   // 3 (side) <- ncu slot
    cudaEventRecord(evB, s2);

    scatter_transpose_kernel<<<64 + (EE + 255) / 256, 256>>>(row, col, attr, W);  // 4 (main)

    cudaStreamWaitEvent(0, evB, 0);   // join: GEMM needs g_h

    dim3 gemm_grid(DD / 128, M_PAD / 128);
    for (int layer = 0; layer < 3; layer++) {
        mma_gemm_kernel<<<gemm_grid, 256, SMEM_GEMM_TOTAL>>>();
        agg_kernel<<<NN, 256>>>(layer == 2 ? out : nullptr);
    }
}

// round 14
// speedup vs baseline: 1.1618x; 1.0359x over previous
#include <cuda_runtime.h>
#include <cuda_fp16.h>
#include <cuda_bf16.h>
#include <cstdint>

#define NN 20000
#define SS 4096
#define EE 640000
#define DD 256
#define M_PAD 20096   // 157 * 128

#define HSCALE     0.00390625f   // 2^-8 (exact)
#define HSCALE_INV 256.0f

// ---------------- scratch (zero-initialized device globals) ----------------
__device__ float  g_h[M_PAD * DD];          // current node features (tf32-rounded)
__device__ __half g_tmph[M_PAD * DD];       // (h @ W) * 2^-8 in fp16 — gather payload
__device__ float  g_wt[DD * DD];            // W^T (K-major), tf32-rounded
__device__ int    g_cnt[NN];
__device__ int    g_off[NN + 1];
__device__ int    g_cur[NN];
__device__ int2   g_edge[EE];               // packed (src_row, attr_bits), CSR order
// embed closed-form tables
__device__ __align__(16) unsigned char g_mtab[SS];
__device__ int g_ck[16];
__device__ int g_dirk[16];

// ---------------- helpers ----------------
__device__ __forceinline__ uint32_t smem_u32(const void* p) {
    uint32_t a;
    asm("{ .reg .u64 t; cvta.to.shared.u64 t, %1; cvt.u32.u64 %0, t; }" : "=r"(a) : "l"(p));
    return a;
}
__device__ __forceinline__ float to_tf32(float x) {
    uint32_t u;
    asm("cvt.rna.tf32.f32 %0, %1;" : "=r"(u) : "f"(x));
    return __uint_as_float(u);
}
#define CP_ASYNC16(s, g) asm volatile("cp.async.cg.shared.global [%0], [%1], 16;" :: "r"(s), "l"(g) : "memory")
#define CP_COMMIT()      asm volatile("cp.async.commit_group;" ::: "memory")
#define CP_WAIT(n)       asm volatile("cp.async.wait_group %0;" :: "n"(n) : "memory")

__device__ __forceinline__ void mma_tf32(float* d, const uint32_t* a, const uint32_t* b) {
    asm volatile(
        "mma.sync.aligned.m16n8k8.row.col.f32.tf32.tf32.f32 "
        "{%0,%1,%2,%3}, {%4,%5,%6,%7}, {%8,%9}, {%0,%1,%2,%3};"
        : "+f"(d[0]), "+f"(d[1]), "+f"(d[2]), "+f"(d[3])
        : "r"(a[0]), "r"(a[1]), "r"(a[2]), "r"(a[3]), "r"(b[0]), "r"(b[1]));
}

// =====================================================================
// prep (block 0) + zero_counts (blocks 1..79)
// =====================================================================
__global__ void prep_zero_kernel(const float* __restrict__ w1, const float* __restrict__ b1) {
    const int tid = threadIdx.x;
    if (blockIdx.x != 0) {
        int i = (blockIdx.x - 1) * 256 + tid;
        if (i < NN) g_cnt[i] = 0;
        return;
    }
    __shared__ int s_B[16];
    __shared__ int s_bnd[16];
    if (tid < 16) {
        float w = w1[tid], b = b1[tid];
        int B, dir;
        if (w > 0.0f) {
            float t = -b / w;
            int cand = (int)floorf(t) - 1;
            if (cand < 0) cand = 0;
            if (cand > SS) cand = SS;
            while (cand < SS && !(fmaf((float)cand, w, b) > 0.0f)) cand++;
            B = cand; dir = 0;
        } else if (w < 0.0f) {
            float t = -b / w;
            int cand = (int)floorf(t) - 1;
            if (cand < 0) cand = 0;
            if (cand > SS) cand = SS;
            while (cand < SS && (fmaf((float)cand, w, b) > 0.0f)) cand++;
            B = cand; dir = 1;
        } else {
            if (b > 0.0f) { B = 0; dir = 0; }
            else          { B = 0; dir = 1; }
        }
        s_B[tid] = B;
        g_dirk[tid] = dir;
    }
    __syncthreads();
    if (tid < 16) {
        int Bk = s_B[tid], pos = 0;
#pragma unroll
        for (int i = 0; i < 16; i++) {
            int Bi = s_B[i];
            if (Bi < Bk || (Bi == Bk && i < tid)) pos++;
        }
        s_bnd[pos] = Bk;
    }
    __syncthreads();
    if (tid < 16) {
        int Bk = s_B[tid], c = 0;
#pragma unroll
        for (int i = 0; i < 16; i++) c += (s_bnd[i] <= Bk) ? 1 : 0;
        g_ck[tid] = c;
    }
    for (int j = tid; j < SS; j += blockDim.x) {
        int m = 0;
#pragma unroll
        for (int i = 0; i < 16; i++) m += (s_bnd[i] <= j) ? 1 : 0;
        g_mtab[j] = (unsigned char)m;
    }
}

// =====================================================================
// Row embedding v3: zero-skip (64B OR-tree) + per-warp bucket atomics
// =====================================================================
__global__ __launch_bounds__(256) void row_embed_kernel(
        const float* __restrict__ init,
        const float* __restrict__ w1, const float* __restrict__ b1,
        const float* __restrict__ w2, const float* __restrict__ b2) {
    __shared__ unsigned char s_mtab[SS];
    __shared__ uint32_t s_buck[8][17];
    __shared__ float s_sufS[18];
    __shared__ int   s_sufC[18];
    __shared__ float s_fin[16];
    const int row = blockIdx.x;
    const int tid = threadIdx.x;
    const int wid = tid >> 5;

    ((uint4*)s_mtab)[tid] = ((const uint4*)g_mtab)[tid];
    if (tid < 136) ((uint32_t*)s_buck)[tid] = 0u;
    __syncthreads();

    const float4* rp = (const float4*)(init + (size_t)row * SS);
    float4 v0 = rp[tid];
    float4 v1 = rp[256 + tid];
    float4 v2 = rp[512 + tid];
    float4 v3 = rp[768 + tid];

    uint32_t any =
        (__float_as_uint(v0.x) | __float_as_uint(v0.y) | __float_as_uint(v0.z) | __float_as_uint(v0.w)) |
        (__float_as_uint(v1.x) | __float_as_uint(v1.y) | __float_as_uint(v1.z) | __float_as_uint(v1.w)) |
        (__float_as_uint(v2.x) | __float_as_uint(v2.y) | __float_as_uint(v2.z) | __float_as_uint(v2.w)) |
        (__float_as_uint(v3.x) | __float_as_uint(v3.y) | __float_as_uint(v3.z) | __float_as_uint(v3.w));

    if (any != 0u) {
        uint32_t* wb = s_buck[wid];
        float4 vv[4] = {v0, v1, v2, v3};
#pragma unroll
        for (int i = 0; i < 4; i++) {
            int j0 = (i * 256 + tid) * 4;
            uint32_t c0 = __float_as_uint(vv[i].x) | __float_as_uint(vv[i].y) |
                          __float_as_uint(vv[i].z) | __float_as_uint(vv[i].w);
            if (c0 != 0u) {
                if (vv[i].x != 0.0f) atomicAdd(&wb[s_mtab[j0    ]], ((uint32_t)(j0    ) << 12) + 1u);
                if (vv[i].y != 0.0f) atomicAdd(&wb[s_mtab[j0 + 1]], ((uint32_t)(j0 + 1) << 12) + 1u);
                if (vv[i].z != 0.0f) atomicAdd(&wb[s_mtab[j0 + 2]], ((uint32_t)(j0 + 2) << 12) + 1u);
                if (vv[i].w != 0.0f) atomicAdd(&wb[s_mtab[j0 + 3]], ((uint32_t)(j0 + 3) << 12) + 1u);
            }
        }
    }
    __syncthreads();

    if (tid == 0) {
        float ss = 0.0f; int sc = 0;
        s_sufS[17] = 0.0f; s_sufC[17] = 0;
        for (int m = 16; m >= 0; m--) {
            uint32_t p = s_buck[0][m] + s_buck[1][m] + s_buck[2][m] + s_buck[3][m] +
                         s_buck[4][m] + s_buck[5][m] + s_buck[6][m] + s_buck[7][m];
            ss += (float)(p >> 12);
            sc += (int)(p & 0xFFFu);
            s_sufS[m] = ss; s_sufC[m] = sc;
        }
    }
    __syncthreads();
    if (tid < 16) {
        int c = g_ck[tid];
        float sumA; int cntA;
        if (g_dirk[tid] == 0) { sumA = s_sufS[c];             cntA = s_sufC[c]; }
        else                  { sumA = s_sufS[0] - s_sufS[c]; cntA = s_sufC[0] - s_sufC[c]; }
        s_fin[tid] = w1[tid] * sumA + b1[tid] * (float)cntA;
    }
    __syncthreads();

    const float cntf = (float)s_sufC[0];
    float val = cntf * b2[tid];
#pragma unroll
    for (int k = 0; k < 16; k++) val = fmaf(s_fin[k], w2[k * DD + tid], val);
    g_h[(size_t)row * DD + tid] = to_tf32(val / fmaxf(cntf, 1.0f));
}

// ---------------- CSR build ----------------
__global__ void count_kernel(const int* __restrict__ col) {
    int e = blockIdx.x * blockDim.x + threadIdx.x;
    if (e < EE) atomicAdd(&g_cnt[col[e]], 1);
}

__global__ void scan_kernel() {
    __shared__ int s_w[32];
    __shared__ int s_carry;
    const int tid = threadIdx.x, lane = tid & 31, wid = tid >> 5;
    if (tid == 0) s_carry = 0;
    __syncthreads();
    for (int base = 0; base < NN; base += 1024) {
        int i = base + tid;
        int v = (i < NN) ? g_cnt[i] : 0;
        int x = v;
#pragma unroll
        for (int off = 1; off < 32; off <<= 1) {
            int t = __shfl_up_sync(0xffffffffu, x, off);
            if (lane >= off) x += t;
        }
        if (lane == 31) s_w[wid] = x;
        __syncthreads();
        if (tid < 32) {
            int y = s_w[tid];
#pragma unroll
            for (int off = 1; off < 32; off <<= 1) {
                int t = __shfl_up_sync(0xffffffffu, y, off);
                if (lane >= off) y += t;
            }
            s_w[tid] = y;
        }
        __syncthreads();
        int carry = s_carry;
        int pre = (wid > 0) ? s_w[wid - 1] : 0;
        int excl = carry + pre + x - v;
        if (i < NN) { g_off[i] = excl; g_cur[i] = excl; }
        __syncthreads();
        if (tid == 0) s_carry = carry + s_w[31];
        __syncthreads();
    }
    if (tid == 0) g_off[NN] = s_carry;
}

// =====================================================================
// transpose W (blocks 0..63) + scatter edges (blocks 64..2563)
// =====================================================================
__global__ void scatter_transpose_kernel(const int* __restrict__ row, const int* __restrict__ col,
                                         const float* __restrict__ attr,
                                         const float* __restrict__ W) {
    const int tid = threadIdx.x;
    if (blockIdx.x < 64) {
        __shared__ float t[32][33];
        const int bx = blockIdx.x & 7;
        const int by = blockIdx.x >> 3;
        const int lx = tid & 31, ly = tid >> 5;
#pragma unroll
        for (int r = 0; r < 4; r++)
            t[ly + r * 8][lx] = to_tf32(W[(bx * 32 + ly + r * 8) * DD + by * 32 + lx]);
        __syncthreads();
#pragma unroll
        for (int r = 0; r < 4; r++)
            g_wt[(by * 32 + ly + r * 8) * DD + bx * 32 + lx] = t[lx][ly + r * 8];
        return;
    }
    int e = (blockIdx.x - 64) * 256 + tid;
    if (e >= EE) return;
    int c = col[e];
    int p = atomicAdd(&g_cur[c], 1);
    g_edge[p] = make_int2(row[e], __float_as_int(attr[e]));
}

// =====================================================================
// tf32 mma.sync GEMM, cp.async double-buffered (BM=BN=128, BK=32)
// epilogue writes half2 scaled by 2^-8 into g_tmph
// =====================================================================
#define ASTR 36
#define TILE_F (128 * ASTR)
#define BUF_BYTES (2 * TILE_F * 4)
#define SMEM_GEMM_TOTAL (2 * BUF_BYTES)     // 73728

__global__ __launch_bounds__(256, 2) void mma_gemm_kernel() {
    extern __shared__ float smem[];
    const int tid = threadIdx.x;
    const int lane = tid & 31;
    const int wid = tid >> 5;
    const int g = lane >> 2, t = lane & 3;
    const int wm = (wid & 1) * 64;
    const int wn = (wid >> 1) * 32;
    const int bn = blockIdx.x * 128;
    const int bm = blockIdx.y * 128;

    const uint32_t sbase = smem_u32(smem);
    const float* Ab = g_h + (size_t)bm * DD;
    const float* Bb = g_wt + (size_t)bn * DD;

    float acc[4][4][4];
#pragma unroll
    for (int i = 0; i < 4; i++)
#pragma unroll
        for (int j = 0; j < 4; j++)
#pragma unroll
            for (int c = 0; c < 4; c++) acc[i][j][c] = 0.0f;

    auto issue = [&](int c, int buf) {
        const uint32_t sa = sbase + buf * BUF_BYTES;
        const uint32_t sb = sa + TILE_F * 4;
        const int k0 = c * 32;
#pragma unroll
        for (int i = 0; i < 4; i++) {
            int task = tid + i * 256;
            int r = task >> 3, q = task & 7;
            CP_ASYNC16(sa + (uint32_t)(r * ASTR + q * 4) * 4,
                       (const char*)(Ab + (size_t)r * DD + k0 + q * 4));
        }
#pragma unroll
        for (int i = 0; i < 4; i++) {
            int task = tid + i * 256;
            int r = task >> 3, q = task & 7;
            CP_ASYNC16(sb + (uint32_t)(r * ASTR + q * 4) * 4,
                       (const char*)(Bb + (size_t)r * DD + k0 + q * 4));
        }
        CP_COMMIT();
    };

    issue(0, 0);

    for (int c = 0; c < 8; c++) {
        __syncthreads();
        if (c < 7) issue(c + 1, (c + 1) & 1);
        if (c < 7) { CP_WAIT(1); } else { CP_WAIT(0); }
        __syncthreads();

        const float* Asp = smem + (c & 1) * (BUF_BYTES / 4);
        const float* Bsp = Asp + TILE_F;
#pragma unroll
        for (int ks = 0; ks < 4; ks++) {
            const int kb = ks * 8;
            uint32_t bf[4][2];
#pragma unroll
            for (int nt = 0; nt < 4; nt++) {
                const float* bp = Bsp + (wn + nt * 8 + g) * ASTR + kb + t;
                bf[nt][0] = __float_as_uint(bp[0]);
                bf[nt][1] = __float_as_uint(bp[4]);
            }
#pragma unroll
            for (int mt = 0; mt < 4; mt++) {
                const int m0 = wm + mt * 16;
                const float* ap0 = Asp + (m0 + g) * ASTR + kb + t;
                const float* ap1 = Asp + (m0 + g + 8) * ASTR + kb + t;
                uint32_t af[4];
                af[0] = __float_as_uint(ap0[0]);
                af[1] = __float_as_uint(ap1[0]);
                af[2] = __float_as_uint(ap0[4]);
                af[3] = __float_as_uint(ap1[4]);
#pragma unroll
                for (int nt = 0; nt < 4; nt++)
                    mma_tf32(acc[mt][nt], af, bf[nt]);
            }
        }
    }

    // epilogue: half2, scaled by 2^-8 (exact)
    __half2* outh = (__half2*)g_tmph;
#pragma unroll
    for (int mt = 0; mt < 4; mt++) {
#pragma unroll
        for (int nt = 0; nt < 4; nt++) {
            const int r0 = bm + wm + mt * 16 + g;
            const int c0 = bn + wn + nt * 8 + 2 * t;   // even
            outh[(size_t)r0 * 128 + (c0 >> 1)] =
                __floats2half2_rn(acc[mt][nt][0] * HSCALE, acc[mt][nt][1] * HSCALE);
            outh[(size_t)(r0 + 8) * 128 + (c0 >> 1)] =
                __floats2half2_rn(acc[mt][nt][2] * HSCALE, acc[mt][nt][3] * HSCALE);
        }
    }
}

// =====================================================================
// agg v4: fp16 payload — 8 warps, each warp gathers a full 512B row
// (32 threads x uint4 = 8 halves each), fp32 accumulation, smem reduce
// =====================================================================
__global__ __launch_bounds__(256) void agg_kernel(float* __restrict__ dst_out) {
    __shared__ float s_red[8][DD];     // 8 KB
    const int c = blockIdx.x;
    const int tid = threadIdx.x;
    const int grp = tid >> 5, lane = tid & 31;
    const int rs = __ldg(&g_off[c]), re = __ldg(&g_off[c + 1]);
    const uint4* __restrict__ tmph = (const uint4*)g_tmph;   // 32 uint4 per row

    float acc[8];
#pragma unroll
    for (int i = 0; i < 8; i++) acc[i] = 0.0f;

    int e = rs + grp;
    for (; e + 8 < re; e += 16) {
        int2 e0 = __ldg(&g_edge[e]);
        int2 e1 = __ldg(&g_edge[e + 8]);
        uint4 v0 = __ldg(&tmph[(size_t)e0.x * 32 + lane]);
        uint4 v1 = __ldg(&tmph[(size_t)e1.x * 32 + lane]);
        float a0 = __int_as_float(e0.y), a1 = __int_as_float(e1.y);
        const __half2* h0 = (const __half2*)&v0;
        const __half2* h1 = (const __half2*)&v1;
#pragma unroll
        for (int i = 0; i < 4; i++) {
            float2 f0 = __half22float2(h0[i]);
            float2 f1 = __half22float2(h1[i]);
            acc[2 * i]     = fmaf(a0, f0.x, acc[2 * i]);
            acc[2 * i + 1] = fmaf(a0, f0.y, acc[2 * i + 1]);
            acc[2 * i]     = fmaf(a1, f1.x, acc[2 * i]);
            acc[2 * i + 1] = fmaf(a1, f1.y, acc[2 * i + 1]);
        }
    }
    if (e < re) {
        int2 e0 = __ldg(&g_edge[e]);
        uint4 v0 = __ldg(&tmph[(size_t)e0.x * 32 + lane]);
        float a0 = __int_as_float(e0.y);
        const __half2* h0 = (const __half2*)&v0;
#pragma unroll
        for (int i = 0; i < 4; i++) {
            float2 f0 = __half22float2(h0[i]);
            acc[2 * i]     = fmaf(a0, f0.x, acc[2 * i]);
            acc[2 * i + 1] = fmaf(a0, f0.y, acc[2 * i + 1]);
        }
    }

#pragma unroll
    for (int i = 0; i < 8; i++) s_red[grp][lane * 8 + i] = acc[i];
    __syncthreads();

    float r = 0.0f;
#pragma unroll
    for (int g2 = 0; g2 < 8; g2++) r += s_red[g2][tid];
    r = fmaxf(r, 0.0f) * HSCALE_INV;    // un-scale after relu (sign-safe: scale > 0)
    if (dst_out) dst_out[(size_t)c * DD + tid] = r;
    else         g_h[(size_t)c * DD + tid] = to_tf32(r);
}

// ---------------- launch ----------------
extern "C" void kernel_launch(void* const* d_in, const int* in_sizes, int n_in,
                              void* d_out, int out_size) {
    const float* init = (const float*)d_in[0];
    const int*   ei   = (const int*)d_in[1];
    const float* attr = (const float*)d_in[2];
    const float* w1   = (const float*)d_in[3];
    const float* b1   = (const float*)d_in[4];
    const float* w2   = (const float*)d_in[5];
    const float* b2   = (const float*)d_in[6];
    const float* W    = (const float*)d_in[7];
    float* out = (float*)d_out;

    const int* row = ei;
    const int* col = ei + EE;

    cudaFuncSetAttribute(mma_gemm_kernel, cudaFuncAttributeMaxDynamicSharedMemorySize,
                         SMEM_GEMM_TOTAL);

    // Fork-join: embed on a side stream concurrent with the CSR chain.
    cudaStream_t s2;
    cudaStreamCreateWithFlags(&s2, cudaStreamNonBlocking);
    cudaEvent_t evA, evB;
    cudaEventCreateWithFlags(&evA, cudaEventDisableTiming);
    cudaEventCreateWithFlags(&evB, cudaEventDisableTiming);

    prep_zero_kernel<<<80, 256>>>(w1, b1);                        // 0 (main)
    cudaEventRecord(evA, 0);

    count_kernel<<<(EE + 255) / 256, 256>>>(col);                 // 1 (main)
    scan_kernel<<<1, 1024>>>();                                   // 2 (main)

    cudaStreamWaitEvent(s2, evA, 0);
    row_embed_kernel<<<NN, 256, 0, s2>>>(init, w1, b1, w2, b2);   // 3 (side) <- ncu slot
    cudaEventRecord(evB, s2);

    scatter_transpose_kernel<<<64 + (EE + 255) / 256, 256>>>(row, col, attr, W);  // 4 (main)

    cudaStreamWaitEvent(0, evB, 0);   // join: GEMM needs g_h

    dim3 gemm_grid(DD / 128, M_PAD / 128);
    for (int layer = 0; layer < 3; layer++) {
        mma_gemm_kernel<<<gemm_grid, 256, SMEM_GEMM_TOTAL>>>();
        agg_kernel<<<NN, 256>>>(layer == 2 ? out : nullptr);
    }
}

// round 15
// speedup vs baseline: 1.1854x; 1.0204x over previous
#include <cuda_runtime.h>
#include <cuda_fp16.h>
#include <cuda_bf16.h>
#include <cstdint>

#define NN 20000
#define SS 4096
#define EE 640000
#define DD 256
#define M_PAD 20096   // 157 * 128

#define HSCALE     0.00390625f   // 2^-8 (exact)
#define HSCALE_INV 256.0f

// ---------------- scratch (zero-initialized device globals) ----------------
__device__ float  g_h[M_PAD * DD];          // current node features (tf32-rounded)
__device__ __half g_tmph[M_PAD * DD];       // (h @ W) * 2^-8 in fp16 — gather payload
__device__ float  g_wt[DD * DD];            // W^T (K-major), tf32-rounded
__device__ int    g_cnt[NN];
__device__ int    g_off[NN + 1];
__device__ int    g_cur[NN];
__device__ int2   g_edge[EE];               // packed (src_row, attr_bits), CSR order
// embed closed-form tables
__device__ __align__(16) unsigned char g_mtab[SS];
__device__ int g_ck[16];
__device__ int g_dirk[16];

// ---------------- helpers ----------------
__device__ __forceinline__ uint32_t smem_u32(const void* p) {
    uint32_t a;
    asm("{ .reg .u64 t; cvta.to.shared.u64 t, %1; cvt.u32.u64 %0, t; }" : "=r"(a) : "l"(p));
    return a;
}
__device__ __forceinline__ float to_tf32(float x) {
    uint32_t u;
    asm("cvt.rna.tf32.f32 %0, %1;" : "=r"(u) : "f"(x));
    return __uint_as_float(u);
}
#define CP_ASYNC16(s, g) asm volatile("cp.async.cg.shared.global [%0], [%1], 16;" :: "r"(s), "l"(g) : "memory")
#define CP_COMMIT()      asm volatile("cp.async.commit_group;" ::: "memory")
#define CP_WAIT(n)       asm volatile("cp.async.wait_group %0;" :: "n"(n) : "memory")

__device__ __forceinline__ void mma_tf32(float* d, const uint32_t* a, const uint32_t* b) {
    asm volatile(
        "mma.sync.aligned.m16n8k8.row.col.f32.tf32.tf32.f32 "
        "{%0,%1,%2,%3}, {%4,%5,%6,%7}, {%8,%9}, {%0,%1,%2,%3};"
        : "+f"(d[0]), "+f"(d[1]), "+f"(d[2]), "+f"(d[3])
        : "r"(a[0]), "r"(a[1]), "r"(a[2]), "r"(a[3]), "r"(b[0]), "r"(b[1]));
}

// =====================================================================
// prep (block 0) + zero_counts (blocks 1..79)
// =====================================================================
__global__ void prep_zero_kernel(const float* __restrict__ w1, const float* __restrict__ b1) {
    const int tid = threadIdx.x;
    if (blockIdx.x != 0) {
        int i = (blockIdx.x - 1) * 256 + tid;
        if (i < NN) g_cnt[i] = 0;
        return;
    }
    __shared__ int s_B[16];
    __shared__ int s_bnd[16];
    if (tid < 16) {
        float w = w1[tid], b = b1[tid];
        int B, dir;
        if (w > 0.0f) {
            float t = -b / w;
            int cand = (int)floorf(t) - 1;
            if (cand < 0) cand = 0;
            if (cand > SS) cand = SS;
            while (cand < SS && !(fmaf((float)cand, w, b) > 0.0f)) cand++;
            B = cand; dir = 0;
        } else if (w < 0.0f) {
            float t = -b / w;
            int cand = (int)floorf(t) - 1;
            if (cand < 0) cand = 0;
            if (cand > SS) cand = SS;
            while (cand < SS && (fmaf((float)cand, w, b) > 0.0f)) cand++;
            B = cand; dir = 1;
        } else {
            if (b > 0.0f) { B = 0; dir = 0; }
            else          { B = 0; dir = 1; }
        }
        s_B[tid] = B;
        g_dirk[tid] = dir;
    }
    __syncthreads();
    if (tid < 16) {
        int Bk = s_B[tid], pos = 0;
#pragma unroll
        for (int i = 0; i < 16; i++) {
            int Bi = s_B[i];
            if (Bi < Bk || (Bi == Bk && i < tid)) pos++;
        }
        s_bnd[pos] = Bk;
    }
    __syncthreads();
    if (tid < 16) {
        int Bk = s_B[tid], c = 0;
#pragma unroll
        for (int i = 0; i < 16; i++) c += (s_bnd[i] <= Bk) ? 1 : 0;
        g_ck[tid] = c;
    }
    for (int j = tid; j < SS; j += blockDim.x) {
        int m = 0;
#pragma unroll
        for (int i = 0; i < 16; i++) m += (s_bnd[i] <= j) ? 1 : 0;
        g_mtab[j] = (unsigned char)m;
    }
}

// =====================================================================
// Row embedding v3: zero-skip (64B OR-tree) + per-warp bucket atomics
// =====================================================================
__global__ __launch_bounds__(256) void row_embed_kernel(
        const float* __restrict__ init,
        const float* __restrict__ w1, const float* __restrict__ b1,
        const float* __restrict__ w2, const float* __restrict__ b2) {
    __shared__ unsigned char s_mtab[SS];
    __shared__ uint32_t s_buck[8][17];
    __shared__ float s_sufS[18];
    __shared__ int   s_sufC[18];
    __shared__ float s_fin[16];
    const int row = blockIdx.x;
    const int tid = threadIdx.x;
    const int wid = tid >> 5;

    ((uint4*)s_mtab)[tid] = ((const uint4*)g_mtab)[tid];
    if (tid < 136) ((uint32_t*)s_buck)[tid] = 0u;
    __syncthreads();

    const float4* rp = (const float4*)(init + (size_t)row * SS);
    float4 v0 = rp[tid];
    float4 v1 = rp[256 + tid];
    float4 v2 = rp[512 + tid];
    float4 v3 = rp[768 + tid];

    uint32_t any =
        (__float_as_uint(v0.x) | __float_as_uint(v0.y) | __float_as_uint(v0.z) | __float_as_uint(v0.w)) |
        (__float_as_uint(v1.x) | __float_as_uint(v1.y) | __float_as_uint(v1.z) | __float_as_uint(v1.w)) |
        (__float_as_uint(v2.x) | __float_as_uint(v2.y) | __float_as_uint(v2.z) | __float_as_uint(v2.w)) |
        (__float_as_uint(v3.x) | __float_as_uint(v3.y) | __float_as_uint(v3.z) | __float_as_uint(v3.w));

    if (any != 0u) {
        uint32_t* wb = s_buck[wid];
        float4 vv[4] = {v0, v1, v2, v3};
#pragma unroll
        for (int i = 0; i < 4; i++) {
            int j0 = (i * 256 + tid) * 4;
            uint32_t c0 = __float_as_uint(vv[i].x) | __float_as_uint(vv[i].y) |
                          __float_as_uint(vv[i].z) | __float_as_uint(vv[i].w);
            if (c0 != 0u) {
                if (vv[i].x != 0.0f) atomicAdd(&wb[s_mtab[j0    ]], ((uint32_t)(j0    ) << 12) + 1u);
                if (vv[i].y != 0.0f) atomicAdd(&wb[s_mtab[j0 + 1]], ((uint32_t)(j0 + 1) << 12) + 1u);
                if (vv[i].z != 0.0f) atomicAdd(&wb[s_mtab[j0 + 2]], ((uint32_t)(j0 + 2) << 12) + 1u);
                if (vv[i].w != 0.0f) atomicAdd(&wb[s_mtab[j0 + 3]], ((uint32_t)(j0 + 3) << 12) + 1u);
            }
        }
    }
    __syncthreads();

    if (tid == 0) {
        float ss = 0.0f; int sc = 0;
        s_sufS[17] = 0.0f; s_sufC[17] = 0;
        for (int m = 16; m >= 0; m--) {
            uint32_t p = s_buck[0][m] + s_buck[1][m] + s_buck[2][m] + s_buck[3][m] +
                         s_buck[4][m] + s_buck[5][m] + s_buck[6][m] + s_buck[7][m];
            ss += (float)(p >> 12);
            sc += (int)(p & 0xFFFu);
            s_sufS[m] = ss; s_sufC[m] = sc;
        }
    }
    __syncthreads();
    if (tid < 16) {
        int c = g_ck[tid];
        float sumA; int cntA;
        if (g_dirk[tid] == 0) { sumA = s_sufS[c];             cntA = s_sufC[c]; }
        else                  { sumA = s_sufS[0] - s_sufS[c]; cntA = s_sufC[0] - s_sufC[c]; }
        s_fin[tid] = w1[tid] * sumA + b1[tid] * (float)cntA;
    }
    __syncthreads();

    const float cntf = (float)s_sufC[0];
    float val = cntf * b2[tid];
#pragma unroll
    for (int k = 0; k < 16; k++) val = fmaf(s_fin[k], w2[k * DD + tid], val);
    g_h[(size_t)row * DD + tid] = to_tf32(val / fmaxf(cntf, 1.0f));
}

// ---------------- CSR build ----------------
__global__ void count_kernel(const int* __restrict__ col) {
    int e = blockIdx.x * blockDim.x + threadIdx.x;
    if (e < EE) atomicAdd(&g_cnt[col[e]], 1);
}

__global__ void scan_kernel() {
    __shared__ int s_w[32];
    __shared__ int s_carry;
    const int tid = threadIdx.x, lane = tid & 31, wid = tid >> 5;
    if (tid == 0) s_carry = 0;
    __syncthreads();
    for (int base = 0; base < NN; base += 1024) {
        int i = base + tid;
        int v = (i < NN) ? g_cnt[i] : 0;
        int x = v;
#pragma unroll
        for (int off = 1; off < 32; off <<= 1) {
            int t = __shfl_up_sync(0xffffffffu, x, off);
            if (lane >= off) x += t;
        }
        if (lane == 31) s_w[wid] = x;
        __syncthreads();
        if (tid < 32) {
            int y = s_w[tid];
#pragma unroll
            for (int off = 1; off < 32; off <<= 1) {
                int t = __shfl_up_sync(0xffffffffu, y, off);
                if (lane >= off) y += t;
            }
            s_w[tid] = y;
        }
        __syncthreads();
        int carry = s_carry;
        int pre = (wid > 0) ? s_w[wid - 1] : 0;
        int excl = carry + pre + x - v;
        if (i < NN) { g_off[i] = excl; g_cur[i] = excl; }
        __syncthreads();
        if (tid == 0) s_carry = carry + s_w[31];
        __syncthreads();
    }
    if (tid == 0) g_off[NN] = s_carry;
}

// =====================================================================
// transpose W (blocks 0..63) + scatter edges (blocks 64..2563)
// =====================================================================
__global__ void scatter_transpose_kernel(const int* __restrict__ row, const int* __restrict__ col,
                                         const float* __restrict__ attr,
                                         const float* __restrict__ W) {
    const int tid = threadIdx.x;
    if (blockIdx.x < 64) {
        __shared__ float t[32][33];
        const int bx = blockIdx.x & 7;
        const int by = blockIdx.x >> 3;
        const int lx = tid & 31, ly = tid >> 5;
#pragma unroll
        for (int r = 0; r < 4; r++)
            t[ly + r * 8][lx] = to_tf32(W[(bx * 32 + ly + r * 8) * DD + by * 32 + lx]);
        __syncthreads();
#pragma unroll
        for (int r = 0; r < 4; r++)
            g_wt[(by * 32 + ly + r * 8) * DD + bx * 32 + lx] = t[lx][ly + r * 8];
        return;
    }
    int e = (blockIdx.x - 64) * 256 + tid;
    if (e >= EE) return;
    int c = col[e];
    int p = atomicAdd(&g_cur[c], 1);
    g_edge[p] = make_int2(row[e], __float_as_int(attr[e]));
}

// =====================================================================
// tf32 mma.sync GEMM, cp.async double-buffered (BM=BN=128, BK=32)
// epilogue writes half2 scaled by 2^-8 into g_tmph
// =====================================================================
#define ASTR 36
#define TILE_F (128 * ASTR)
#define BUF_BYTES (2 * TILE_F * 4)
#define SMEM_GEMM_TOTAL (2 * BUF_BYTES)     // 73728

__global__ __launch_bounds__(256, 2) void mma_gemm_kernel() {
    extern __shared__ float smem[];
    const int tid = threadIdx.x;
    const int lane = tid & 31;
    const int wid = tid >> 5;
    const int g = lane >> 2, t = lane & 3;
    const int wm = (wid & 1) * 64;
    const int wn = (wid >> 1) * 32;
    const int bn = blockIdx.x * 128;
    const int bm = blockIdx.y * 128;

    const uint32_t sbase = smem_u32(smem);
    const float* Ab = g_h + (size_t)bm * DD;
    const float* Bb = g_wt + (size_t)bn * DD;

    float acc[4][4][4];
#pragma unroll
    for (int i = 0; i < 4; i++)
#pragma unroll
        for (int j = 0; j < 4; j++)
#pragma unroll
            for (int c = 0; c < 4; c++) acc[i][j][c] = 0.0f;

    auto issue = [&](int c, int buf) {
        const uint32_t sa = sbase + buf * BUF_BYTES;
        const uint32_t sb = sa + TILE_F * 4;
        const int k0 = c * 32;
#pragma unroll
        for (int i = 0; i < 4; i++) {
            int task = tid + i * 256;
            int r = task >> 3, q = task & 7;
            CP_ASYNC16(sa + (uint32_t)(r * ASTR + q * 4) * 4,
                       (const char*)(Ab + (size_t)r * DD + k0 + q * 4));
        }
#pragma unroll
        for (int i = 0; i < 4; i++) {
            int task = tid + i * 256;
            int r = task >> 3, q = task & 7;
            CP_ASYNC16(sb + (uint32_t)(r * ASTR + q * 4) * 4,
                       (const char*)(Bb + (size_t)r * DD + k0 + q * 4));
        }
        CP_COMMIT();
    };

    issue(0, 0);

    for (int c = 0; c < 8; c++) {
        __syncthreads();
        if (c < 7) issue(c + 1, (c + 1) & 1);
        if (c < 7) { CP_WAIT(1); } else { CP_WAIT(0); }
        __syncthreads();

        const float* Asp = smem + (c & 1) * (BUF_BYTES / 4);
        const float* Bsp = Asp + TILE_F;
#pragma unroll
        for (int ks = 0; ks < 4; ks++) {
            const int kb = ks * 8;
            uint32_t bf[4][2];
#pragma unroll
            for (int nt = 0; nt < 4; nt++) {
                const float* bp = Bsp + (wn + nt * 8 + g) * ASTR + kb + t;
                bf[nt][0] = __float_as_uint(bp[0]);
                bf[nt][1] = __float_as_uint(bp[4]);
            }
#pragma unroll
            for (int mt = 0; mt < 4; mt++) {
                const int m0 = wm + mt * 16;
                const float* ap0 = Asp + (m0 + g) * ASTR + kb + t;
                const float* ap1 = Asp + (m0 + g + 8) * ASTR + kb + t;
                uint32_t af[4];
                af[0] = __float_as_uint(ap0[0]);
                af[1] = __float_as_uint(ap1[0]);
                af[2] = __float_as_uint(ap0[4]);
                af[3] = __float_as_uint(ap1[4]);
#pragma unroll
                for (int nt = 0; nt < 4; nt++)
                    mma_tf32(acc[mt][nt], af, bf[nt]);
            }
        }
    }

    // epilogue: half2, scaled by 2^-8 (exact)
    __half2* outh = (__half2*)g_tmph;
#pragma unroll
    for (int mt = 0; mt < 4; mt++) {
#pragma unroll
        for (int nt = 0; nt < 4; nt++) {
            const int r0 = bm + wm + mt * 16 + g;
            const int c0 = bn + wn + nt * 8 + 2 * t;   // even
            outh[(size_t)r0 * 128 + (c0 >> 1)] =
                __floats2half2_rn(acc[mt][nt][0] * HSCALE, acc[mt][nt][1] * HSCALE);
            outh[(size_t)(r0 + 8) * 128 + (c0 >> 1)] =
                __floats2half2_rn(acc[mt][nt][2] * HSCALE, acc[mt][nt][3] * HSCALE);
        }
    }
}

// =====================================================================
// agg v5: fp16 payload, MLP-4 — each warp batches 4 edges (stride 8)
// =====================================================================
__global__ __launch_bounds__(256) void agg_kernel(float* __restrict__ dst_out) {
    __shared__ float s_red[8][DD];     // 8 KB
    const int c = blockIdx.x;
    const int tid = threadIdx.x;
    const int grp = tid >> 5, lane = tid & 31;
    const int rs = __ldg(&g_off[c]), re = __ldg(&g_off[c + 1]);
    const uint4* __restrict__ tmph = (const uint4*)g_tmph;   // 32 uint4 per row

    float acc[8];
#pragma unroll
    for (int i = 0; i < 8; i++) acc[i] = 0.0f;

    int e = rs + grp;
    // main loop: 4 edges in flight per warp (e, e+8, e+16, e+24)
    for (; e + 24 < re; e += 32) {
        int2 ed[4];
#pragma unroll
        for (int i = 0; i < 4; i++) ed[i] = __ldg(&g_edge[e + i * 8]);
        uint4 v[4];
#pragma unroll
        for (int i = 0; i < 4; i++) v[i] = __ldg(&tmph[(size_t)ed[i].x * 32 + lane]);
#pragma unroll
        for (int i = 0; i < 4; i++) {
            float a = __int_as_float(ed[i].y);
            const __half2* h = (const __half2*)&v[i];
#pragma unroll
            for (int q = 0; q < 4; q++) {
                float2 f = __half22float2(h[q]);
                acc[2 * q]     = fmaf(a, f.x, acc[2 * q]);
                acc[2 * q + 1] = fmaf(a, f.y, acc[2 * q + 1]);
            }
        }
    }
    // tail: single edge per step
    for (; e < re; e += 8) {
        int2 e0 = __ldg(&g_edge[e]);
        uint4 v0 = __ldg(&tmph[(size_t)e0.x * 32 + lane]);
        float a0 = __int_as_float(e0.y);
        const __half2* h0 = (const __half2*)&v0;
#pragma unroll
        for (int q = 0; q < 4; q++) {
            float2 f = __half22float2(h0[q]);
            acc[2 * q]     = fmaf(a0, f.x, acc[2 * q]);
            acc[2 * q + 1] = fmaf(a0, f.y, acc[2 * q + 1]);
        }
    }

#pragma unroll
    for (int i = 0; i < 8; i++) s_red[grp][lane * 8 + i] = acc[i];
    __syncthreads();

    float r = 0.0f;
#pragma unroll
    for (int g2 = 0; g2 < 8; g2++) r += s_red[g2][tid];
    r = fmaxf(r, 0.0f) * HSCALE_INV;    // un-scale after relu (sign-safe)
    if (dst_out) dst_out[(size_t)c * DD + tid] = r;
    else         g_h[(size_t)c * DD + tid] = to_tf32(r);
}

// ---------------- launch ----------------
extern "C" void kernel_launch(void* const* d_in, const int* in_sizes, int n_in,
                              void* d_out, int out_size) {
    const float* init = (const float*)d_in[0];
    const int*   ei   = (const int*)d_in[1];
    const float* attr = (const float*)d_in[2];
    const float* w1   = (const float*)d_in[3];
    const float* b1   = (const float*)d_in[4];
    const float* w2   = (const float*)d_in[5];
    const float* b2   = (const float*)d_in[6];
    const float* W    = (const float*)d_in[7];
    float* out = (float*)d_out;

    const int* row = ei;
    const int* col = ei + EE;

    cudaFuncSetAttribute(mma_gemm_kernel, cudaFuncAttributeMaxDynamicSharedMemorySize,
                         SMEM_GEMM_TOTAL);

    // Fork-join: embed on a side stream concurrent with the CSR chain.
    cudaStream_t s2;
    cudaStreamCreateWithFlags(&s2, cudaStreamNonBlocking);
    cudaEvent_t evA, evB;
    cudaEventCreateWithFlags(&evA, cudaEventDisableTiming);
    cudaEventCreateWithFlags(&evB, cudaEventDisableTiming);

    prep_zero_kernel<<<80, 256>>>(w1, b1);                        // 0 (main)
    cudaEventRecord(evA, 0);

    count_kernel<<<(EE + 255) / 256, 256>>>(col);                 // 1 (main)
    scan_kernel<<<1, 1024>>>();                                   // 2 (main)

    cudaStreamWaitEvent(s2, evA, 0);
    row_embed_kernel<<<NN, 256, 0, s2>>>(init, w1, b1, w2, b2);   // 3 (side) <- ncu slot
    cudaEventRecord(evB, s2);

    scatter_transpose_kernel<<<64 + (EE + 255) / 256, 256>>>(row, col, attr, W);  // 4 (main)

    cudaStreamWaitEvent(0, evB, 0);   // join: GEMM needs g_h

    dim3 gemm_grid(DD / 128, M_PAD / 128);
    for (int layer = 0; layer < 3; layer++) {
        mma_gemm_kernel<<<gemm_grid, 256, SMEM_GEMM_TOTAL>>>();
        agg_kernel<<<NN, 256>>>(layer == 2 ? out : nullptr);
    }
}

// round 16
// speedup vs baseline: 1.3171x; 1.1110x over previous
#include <cuda_runtime.h>
#include <cuda_fp16.h>
#include <cuda_bf16.h>
#include <cstdint>

#define NN 20000
#define SS 4096
#define EE 640000
#define DD 256
#define M_PAD 20096   // 157 * 128

#define HSCALE     0.00390625f   // 2^-8 (exact)
#define HSCALE_INV 256.0f

// ---------------- scratch (zero-initialized device globals) ----------------
__device__ float  g_h[M_PAD * DD];          // current node features (tf32-rounded)
__device__ __half g_tmph[M_PAD * DD];       // (h @ W) * 2^-8 in fp16 — gather payload
__device__ float  g_wt[DD * DD];            // W^T (K-major), tf32-rounded
__device__ int    g_cnt[NN];
__device__ int    g_off[NN + 1];
__device__ int    g_cur[NN];
__device__ int2   g_edge[EE];               // packed (src_row, attr_bits), CSR order
// embed closed-form tables
__device__ __align__(16) unsigned char g_mtab[SS];
__device__ int g_ck[16];
__device__ int g_dirk[16];

// ---------------- helpers ----------------
__device__ __forceinline__ uint32_t smem_u32(const void* p) {
    uint32_t a;
    asm("{ .reg .u64 t; cvta.to.shared.u64 t, %1; cvt.u32.u64 %0, t; }" : "=r"(a) : "l"(p));
    return a;
}
__device__ __forceinline__ float to_tf32(float x) {
    uint32_t u;
    asm("cvt.rna.tf32.f32 %0, %1;" : "=r"(u) : "f"(x));
    return __uint_as_float(u);
}
#define CP_ASYNC16(s, g) asm volatile("cp.async.cg.shared.global [%0], [%1], 16;" :: "r"(s), "l"(g) : "memory")
#define CP_COMMIT()      asm volatile("cp.async.commit_group;" ::: "memory")
#define CP_WAIT(n)       asm volatile("cp.async.wait_group %0;" :: "n"(n) : "memory")

__device__ __forceinline__ void mma_tf32(float* d, const uint32_t* a, const uint32_t* b) {
    asm volatile(
        "mma.sync.aligned.m16n8k8.row.col.f32.tf32.tf32.f32 "
        "{%0,%1,%2,%3}, {%4,%5,%6,%7}, {%8,%9}, {%0,%1,%2,%3};"
        : "+f"(d[0]), "+f"(d[1]), "+f"(d[2]), "+f"(d[3])
        : "r"(a[0]), "r"(a[1]), "r"(a[2]), "r"(a[3]), "r"(b[0]), "r"(b[1]));
}

// =====================================================================
// prep (block 0) + zero_counts (blocks 1..79)
// =====================================================================
__global__ void prep_zero_kernel(const float* __restrict__ w1, const float* __restrict__ b1) {
    const int tid = threadIdx.x;
    if (blockIdx.x != 0) {
        int i = (blockIdx.x - 1) * 256 + tid;
        if (i < NN) g_cnt[i] = 0;
        return;
    }
    __shared__ int s_B[16];
    __shared__ int s_bnd[16];
    if (tid < 16) {
        float w = w1[tid], b = b1[tid];
        int B, dir;
        if (w > 0.0f) {
            float t = -b / w;
            int cand = (int)floorf(t) - 1;
            if (cand < 0) cand = 0;
            if (cand > SS) cand = SS;
            while (cand < SS && !(fmaf((float)cand, w, b) > 0.0f)) cand++;
            B = cand; dir = 0;
        } else if (w < 0.0f) {
            float t = -b / w;
            int cand = (int)floorf(t) - 1;
            if (cand < 0) cand = 0;
            if (cand > SS) cand = SS;
            while (cand < SS && (fmaf((float)cand, w, b) > 0.0f)) cand++;
            B = cand; dir = 1;
        } else {
            if (b > 0.0f) { B = 0; dir = 0; }
            else          { B = 0; dir = 1; }
        }
        s_B[tid] = B;
        g_dirk[tid] = dir;
    }
    __syncthreads();
    if (tid < 16) {
        int Bk = s_B[tid], pos = 0;
#pragma unroll
        for (int i = 0; i < 16; i++) {
            int Bi = s_B[i];
            if (Bi < Bk || (Bi == Bk && i < tid)) pos++;
        }
        s_bnd[pos] = Bk;
    }
    __syncthreads();
    if (tid < 16) {
        int Bk = s_B[tid], c = 0;
#pragma unroll
        for (int i = 0; i < 16; i++) c += (s_bnd[i] <= Bk) ? 1 : 0;
        g_ck[tid] = c;
    }
    for (int j = tid; j < SS; j += blockDim.x) {
        int m = 0;
#pragma unroll
        for (int i = 0; i < 16; i++) m += (s_bnd[i] <= j) ? 1 : 0;
        g_mtab[j] = (unsigned char)m;
    }
}

// =====================================================================
// Row embedding v3: zero-skip (64B OR-tree) + per-warp bucket atomics
// =====================================================================
__global__ __launch_bounds__(256) void row_embed_kernel(
        const float* __restrict__ init,
        const float* __restrict__ w1, const float* __restrict__ b1,
        const float* __restrict__ w2, const float* __restrict__ b2) {
    __shared__ unsigned char s_mtab[SS];
    __shared__ uint32_t s_buck[8][17];
    __shared__ float s_sufS[18];
    __shared__ int   s_sufC[18];
    __shared__ float s_fin[16];
    const int row = blockIdx.x;
    const int tid = threadIdx.x;
    const int wid = tid >> 5;

    ((uint4*)s_mtab)[tid] = ((const uint4*)g_mtab)[tid];
    if (tid < 136) ((uint32_t*)s_buck)[tid] = 0u;
    __syncthreads();

    const float4* rp = (const float4*)(init + (size_t)row * SS);
    float4 v0 = rp[tid];
    float4 v1 = rp[256 + tid];
    float4 v2 = rp[512 + tid];
    float4 v3 = rp[768 + tid];

    uint32_t any =
        (__float_as_uint(v0.x) | __float_as_uint(v0.y) | __float_as_uint(v0.z) | __float_as_uint(v0.w)) |
        (__float_as_uint(v1.x) | __float_as_uint(v1.y) | __float_as_uint(v1.z) | __float_as_uint(v1.w)) |
        (__float_as_uint(v2.x) | __float_as_uint(v2.y) | __float_as_uint(v2.z) | __float_as_uint(v2.w)) |
        (__float_as_uint(v3.x) | __float_as_uint(v3.y) | __float_as_uint(v3.z) | __float_as_uint(v3.w));

    if (any != 0u) {
        uint32_t* wb = s_buck[wid];
        float4 vv[4] = {v0, v1, v2, v3};
#pragma unroll
        for (int i = 0; i < 4; i++) {
            int j0 = (i * 256 + tid) * 4;
            uint32_t c0 = __float_as_uint(vv[i].x) | __float_as_uint(vv[i].y) |
                          __float_as_uint(vv[i].z) | __float_as_uint(vv[i].w);
            if (c0 != 0u) {
                if (vv[i].x != 0.0f) atomicAdd(&wb[s_mtab[j0    ]], ((uint32_t)(j0    ) << 12) + 1u);
                if (vv[i].y != 0.0f) atomicAdd(&wb[s_mtab[j0 + 1]], ((uint32_t)(j0 + 1) << 12) + 1u);
                if (vv[i].z != 0.0f) atomicAdd(&wb[s_mtab[j0 + 2]], ((uint32_t)(j0 + 2) << 12) + 1u);
                if (vv[i].w != 0.0f) atomicAdd(&wb[s_mtab[j0 + 3]], ((uint32_t)(j0 + 3) << 12) + 1u);
            }
        }
    }
    __syncthreads();

    if (tid == 0) {
        float ss = 0.0f; int sc = 0;
        s_sufS[17] = 0.0f; s_sufC[17] = 0;
        for (int m = 16; m >= 0; m--) {
            uint32_t p = s_buck[0][m] + s_buck[1][m] + s_buck[2][m] + s_buck[3][m] +
                         s_buck[4][m] + s_buck[5][m] + s_buck[6][m] + s_buck[7][m];
            ss += (float)(p >> 12);
            sc += (int)(p & 0xFFFu);
            s_sufS[m] = ss; s_sufC[m] = sc;
        }
    }
    __syncthreads();
    if (tid < 16) {
        int c = g_ck[tid];
        float sumA; int cntA;
        if (g_dirk[tid] == 0) { sumA = s_sufS[c];             cntA = s_sufC[c]; }
        else                  { sumA = s_sufS[0] - s_sufS[c]; cntA = s_sufC[0] - s_sufC[c]; }
        s_fin[tid] = w1[tid] * sumA + b1[tid] * (float)cntA;
    }
    __syncthreads();

    const float cntf = (float)s_sufC[0];
    float val = cntf * b2[tid];
#pragma unroll
    for (int k = 0; k < 16; k++) val = fmaf(s_fin[k], w2[k * DD + tid], val);
    g_h[(size_t)row * DD + tid] = to_tf32(val / fmaxf(cntf, 1.0f));
}

// ---------------- CSR build ----------------
__global__ void count_kernel(const int* __restrict__ col) {
    int e = blockIdx.x * blockDim.x + threadIdx.x;
    if (e < EE) atomicAdd(&g_cnt[col[e]], 1);
}

__global__ void scan_kernel() {
    __shared__ int s_w[32];
    __shared__ int s_carry;
    const int tid = threadIdx.x, lane = tid & 31, wid = tid >> 5;
    if (tid == 0) s_carry = 0;
    __syncthreads();
    for (int base = 0; base < NN; base += 1024) {
        int i = base + tid;
        int v = (i < NN) ? g_cnt[i] : 0;
        int x = v;
#pragma unroll
        for (int off = 1; off < 32; off <<= 1) {
            int t = __shfl_up_sync(0xffffffffu, x, off);
            if (lane >= off) x += t;
        }
        if (lane == 31) s_w[wid] = x;
        __syncthreads();
        if (tid < 32) {
            int y = s_w[tid];
#pragma unroll
            for (int off = 1; off < 32; off <<= 1) {
                int t = __shfl_up_sync(0xffffffffu, y, off);
                if (lane >= off) y += t;
            }
            s_w[tid] = y;
        }
        __syncthreads();
        int carry = s_carry;
        int pre = (wid > 0) ? s_w[wid - 1] : 0;
        int excl = carry + pre + x - v;
        if (i < NN) { g_off[i] = excl; g_cur[i] = excl; }
        __syncthreads();
        if (tid == 0) s_carry = carry + s_w[31];
        __syncthreads();
    }
    if (tid == 0) g_off[NN] = s_carry;
}

// =====================================================================
// transpose W (blocks 0..63) + scatter edges (blocks 64..2563)
// =====================================================================
__global__ void scatter_transpose_kernel(const int* __restrict__ row, const int* __restrict__ col,
                                         const float* __restrict__ attr,
                                         const float* __restrict__ W) {
    const int tid = threadIdx.x;
    if (blockIdx.x < 64) {
        __shared__ float t[32][33];
        const int bx = blockIdx.x & 7;
        const int by = blockIdx.x >> 3;
        const int lx = tid & 31, ly = tid >> 5;
#pragma unroll
        for (int r = 0; r < 4; r++)
            t[ly + r * 8][lx] = to_tf32(W[(bx * 32 + ly + r * 8) * DD + by * 32 + lx]);
        __syncthreads();
#pragma unroll
        for (int r = 0; r < 4; r++)
            g_wt[(by * 32 + ly + r * 8) * DD + bx * 32 + lx] = t[lx][ly + r * 8];
        return;
    }
    int e = (blockIdx.x - 64) * 256 + tid;
    if (e >= EE) return;
    int c = col[e];
    int p = atomicAdd(&g_cur[c], 1);
    g_edge[p] = make_int2(row[e], __float_as_int(attr[e]));
}

// =====================================================================
// tf32 mma.sync GEMM, cp.async double-buffered (BM=BN=128, BK=32)
// epilogue writes half2 scaled by 2^-8 into g_tmph
// =====================================================================
#define ASTR 36
#define TILE_F (128 * ASTR)
#define BUF_BYTES (2 * TILE_F * 4)
#define SMEM_GEMM_TOTAL (2 * BUF_BYTES)     // 73728

__global__ __launch_bounds__(256, 2) void mma_gemm_kernel() {
    extern __shared__ float smem[];
    const int tid = threadIdx.x;
    const int lane = tid & 31;
    const int wid = tid >> 5;
    const int g = lane >> 2, t = lane & 3;
    const int wm = (wid & 1) * 64;
    const int wn = (wid >> 1) * 32;
    const int bn = blockIdx.x * 128;
    const int bm = blockIdx.y * 128;

    const uint32_t sbase = smem_u32(smem);
    const float* Ab = g_h + (size_t)bm * DD;
    const float* Bb = g_wt + (size_t)bn * DD;

    float acc[4][4][4];
#pragma unroll
    for (int i = 0; i < 4; i++)
#pragma unroll
        for (int j = 0; j < 4; j++)
#pragma unroll
            for (int c = 0; c < 4; c++) acc[i][j][c] = 0.0f;

    auto issue = [&](int c, int buf) {
        const uint32_t sa = sbase + buf * BUF_BYTES;
        const uint32_t sb = sa + TILE_F * 4;
        const int k0 = c * 32;
#pragma unroll
        for (int i = 0; i < 4; i++) {
            int task = tid + i * 256;
            int r = task >> 3, q = task & 7;
            CP_ASYNC16(sa + (uint32_t)(r * ASTR + q * 4) * 4,
                       (const char*)(Ab + (size_t)r * DD + k0 + q * 4));
        }
#pragma unroll
        for (int i = 0; i < 4; i++) {
            int task = tid + i * 256;
            int r = task >> 3, q = task & 7;
            CP_ASYNC16(sb + (uint32_t)(r * ASTR + q * 4) * 4,
                       (const char*)(Bb + (size_t)r * DD + k0 + q * 4));
        }
        CP_COMMIT();
    };

    issue(0, 0);

    for (int c = 0; c < 8; c++) {
        __syncthreads();
        if (c < 7) issue(c + 1, (c + 1) & 1);
        if (c < 7) { CP_WAIT(1); } else { CP_WAIT(0); }
        __syncthreads();

        const float* Asp = smem + (c & 1) * (BUF_BYTES / 4);
        const float* Bsp = Asp + TILE_F;
#pragma unroll
        for (int ks = 0; ks < 4; ks++) {
            const int kb = ks * 8;
            uint32_t bf[4][2];
#pragma unroll
            for (int nt = 0; nt < 4; nt++) {
                const float* bp = Bsp + (wn + nt * 8 + g) * ASTR + kb + t;
                bf[nt][0] = __float_as_uint(bp[0]);
                bf[nt][1] = __float_as_uint(bp[4]);
            }
#pragma unroll
            for (int mt = 0; mt < 4; mt++) {
                const int m0 = wm + mt * 16;
                const float* ap0 = Asp + (m0 + g) * ASTR + kb + t;
                const float* ap1 = Asp + (m0 + g + 8) * ASTR + kb + t;
                uint32_t af[4];
                af[0] = __float_as_uint(ap0[0]);
                af[1] = __float_as_uint(ap1[0]);
                af[2] = __float_as_uint(ap0[4]);
                af[3] = __float_as_uint(ap1[4]);
#pragma unroll
                for (int nt = 0; nt < 4; nt++)
                    mma_tf32(acc[mt][nt], af, bf[nt]);
            }
        }
    }

    // epilogue: half2, scaled by 2^-8 (exact)
    __half2* outh = (__half2*)g_tmph;
#pragma unroll
    for (int mt = 0; mt < 4; mt++) {
#pragma unroll
        for (int nt = 0; nt < 4; nt++) {
            const int r0 = bm + wm + mt * 16 + g;
            const int c0 = bn + wn + nt * 8 + 2 * t;   // even
            outh[(size_t)r0 * 128 + (c0 >> 1)] =
                __floats2half2_rn(acc[mt][nt][0] * HSCALE, acc[mt][nt][1] * HSCALE);
            outh[(size_t)(r0 + 8) * 128 + (c0 >> 1)] =
                __floats2half2_rn(acc[mt][nt][2] * HSCALE, acc[mt][nt][3] * HSCALE);
        }
    }
}

// =====================================================================
// agg v6: one warp per destination — no smem, no block sync
// 2500 blocks x 8 warps; warp gathers its dest's edges (batch-4 MLP),
// lane l accumulates halves [8l..8l+8), writes 2 float4 directly.
// =====================================================================
__global__ __launch_bounds__(256) void agg_kernel(float* __restrict__ dst_out) {
    const int wid = threadIdx.x >> 5, lane = threadIdx.x & 31;
    const int c = blockIdx.x * 8 + wid;
    const int rs = __ldg(&g_off[c]), re = __ldg(&g_off[c + 1]);
    const uint4* __restrict__ tmph = (const uint4*)g_tmph;   // 32 uint4 per row

    float acc[8];
#pragma unroll
    for (int i = 0; i < 8; i++) acc[i] = 0.0f;

    int e = rs;
    for (; e + 3 < re; e += 4) {
        int2 ed[4];
#pragma unroll
        for (int i = 0; i < 4; i++) ed[i] = __ldg(&g_edge[e + i]);
        uint4 v[4];
#pragma unroll
        for (int i = 0; i < 4; i++) v[i] = __ldg(&tmph[(size_t)ed[i].x * 32 + lane]);
#pragma unroll
        for (int i = 0; i < 4; i++) {
            float a = __int_as_float(ed[i].y);
            const __half2* h = (const __half2*)&v[i];
#pragma unroll
            for (int q = 0; q < 4; q++) {
                float2 f = __half22float2(h[q]);
                acc[2 * q]     = fmaf(a, f.x, acc[2 * q]);
                acc[2 * q + 1] = fmaf(a, f.y, acc[2 * q + 1]);
            }
        }
    }
    for (; e < re; e++) {
        int2 e0 = __ldg(&g_edge[e]);
        uint4 v0 = __ldg(&tmph[(size_t)e0.x * 32 + lane]);
        float a0 = __int_as_float(e0.y);
        const __half2* h0 = (const __half2*)&v0;
#pragma unroll
        for (int q = 0; q < 4; q++) {
            float2 f = __half22float2(h0[q]);
            acc[2 * q]     = fmaf(a0, f.x, acc[2 * q]);
            acc[2 * q + 1] = fmaf(a0, f.y, acc[2 * q + 1]);
        }
    }

    float r[8];
#pragma unroll
    for (int i = 0; i < 8; i++) r[i] = fmaxf(acc[i], 0.0f) * HSCALE_INV;

    if (dst_out) {
        float* dp = dst_out + (size_t)c * DD + lane * 8;
        *(float4*)(dp)     = make_float4(r[0], r[1], r[2], r[3]);
        *(float4*)(dp + 4) = make_float4(r[4], r[5], r[6], r[7]);
    } else {
        float* hp = g_h + (size_t)c * DD + lane * 8;
        *(float4*)(hp)     = make_float4(to_tf32(r[0]), to_tf32(r[1]), to_tf32(r[2]), to_tf32(r[3]));
        *(float4*)(hp + 4) = make_float4(to_tf32(r[4]), to_tf32(r[5]), to_tf32(r[6]), to_tf32(r[7]));
    }
}

// ---------------- launch ----------------
extern "C" void kernel_launch(void* const* d_in, const int* in_sizes, int n_in,
                              void* d_out, int out_size) {
    const float* init = (const float*)d_in[0];
    const int*   ei   = (const int*)d_in[1];
    const float* attr = (const float*)d_in[2];
    const float* w1   = (const float*)d_in[3];
    const float* b1   = (const float*)d_in[4];
    const float* w2   = (const float*)d_in[5];
    const float* b2   = (const float*)d_in[6];
    const float* W    = (const float*)d_in[7];
    float* out = (float*)d_out;

    const int* row = ei;
    const int* col = ei + EE;

    cudaFuncSetAttribute(mma_gemm_kernel, cudaFuncAttributeMaxDynamicSharedMemorySize,
                         SMEM_GEMM_TOTAL);

    // Fork-join: embed on a side stream concurrent with the CSR chain.
    cudaStream_t s2;
    cudaStreamCreateWithFlags(&s2, cudaStreamNonBlocking);
    cudaEvent_t evA, evB;
    cudaEventCreateWithFlags(&evA, cudaEventDisableTiming);
    cudaEventCreateWithFlags(&evB, cudaEventDisableTiming);

    prep_zero_kernel<<<80, 256>>>(w1, b1);                        // 0 (main)
    cudaEventRecord(evA, 0);

    count_kernel<<<(EE + 255) / 256, 256>>>(col);                 // 1 (main)
    scan_kernel<<<1, 1024>>>();                                   // 2 (main)

    cudaStreamWaitEvent(s2, evA, 0);
    row_embed_kernel<<<NN, 256, 0, s2>>>(init, w1, b1, w2, b2);   // 3 (side) <- ncu slot
    cudaEventRecord(evB, s2);

    scatter_transpose_kernel<<<64 + (EE + 255) / 256, 256>>>(row, col, attr, W);  // 4 (main)

    cudaStreamWaitEvent(0, evB, 0);   // join: GEMM needs g_h

    dim3 gemm_grid(DD / 128, M_PAD / 128);
    for (int layer = 0; layer < 3; layer++) {
        mma_gemm_kernel<<<gemm_grid, 256, SMEM_GEMM_TOTAL>>>();
        agg_kernel<<<NN / 8, 256>>>(layer == 2 ? out : nullptr);
    }
}